// round 1
// baseline (speedup 1.0000x reference)
#include <cuda_runtime.h>
#include <math.h>

// Problem constants
#define B_SZ    2
#define T_SEQ   1024
#define D_INF   1024
#define D_MEM   256
#define VOCAB   32000
#define PHASE_N 8
#define MARGIN_N 4
#define M_ROWS  (B_SZ * T_SEQ)   // 2048

// Output layout offsets (float elements), concatenated in reference return order
#define OFF_MEM   0                          // 2*256*256       = 131072
#define OFF_SUM   131072                     // 2*1024*256      = 524288
#define OFF_LB    655360                     // 2*1024*32000    = 65536000
#define OFF_PH    66191360                   // 2*1024*8        = 16384
#define OFF_WIN   66207744                   // 2*1024*32000    = 65536000
#define OFF_MAR   131743744                  // 2*1024*4        = 8192

// Scratch (no cudaMalloc allowed): device globals
__device__ float g_k   [M_ROWS * D_MEM];
__device__ float g_v   [M_ROWS * D_MEM];
__device__ float g_beta[M_ROWS * D_MEM];
__device__ float g_lam [M_ROWS * D_MEM];
__device__ float g_sraw[M_ROWS * D_MEM];

// ---------------- packed f32x2 helpers (Blackwell FFMA2) ----------------
__device__ __forceinline__ unsigned long long pack2(float x, float y) {
    unsigned long long r;
    asm("mov.b64 %0, {%1, %2};" : "=l"(r) : "f"(x), "f"(y));
    return r;
}
__device__ __forceinline__ void unpack2(unsigned long long p, float& x, float& y) {
    asm("mov.b64 {%0, %1}, %2;" : "=f"(x), "=f"(y) : "l"(p));
}
__device__ __forceinline__ void ffma2(unsigned long long& d, unsigned long long a,
                                      unsigned long long b) {
    asm("fma.rn.f32x2 %0, %1, %2, %0;" : "+l"(d) : "l"(a), "l"(b));
}

// ---------------- generic GEMM: C[M,N] = A[M,K] @ B[N,K]^T + bias, + act ----
// ACT: 0 = none, 1 = sigmoid, 2 = tanh
// BM=64, BN=64, BK=16, 256 threads, 4x4 micro-tile per thread.
// M must be a multiple of 64, K a multiple of 16; N arbitrary (guarded).
template <int ACT>
__global__ __launch_bounds__(256)
void gemm_bias_act(const float* __restrict__ A, const float* __restrict__ B,
                   const float* __restrict__ bias, float* __restrict__ C,
                   int M, int N, int K)
{
    __shared__ float As[16][68];
    __shared__ float Bs[16][68];

    const int tid = threadIdx.x;
    const int m0 = blockIdx.y * 64;
    const int n0 = blockIdx.x * 64;
    const int ty = tid >> 4;         // 0..15
    const int tx = tid & 15;         // 0..15
    const int lr = tid >> 2;         // 0..63  (tile row loaded)
    const int lc = (tid & 3) << 2;   // 0,4,8,12 (k offset within tile)

    unsigned long long acc[4][2];
    #pragma unroll
    for (int i = 0; i < 4; i++) { acc[i][0] = 0ull; acc[i][1] = 0ull; }

    for (int k0 = 0; k0 < K; k0 += 16) {
        // A tile load (M multiple of 64 -> no row guard)
        float4 av = *(const float4*)(A + (size_t)(m0 + lr) * K + k0 + lc);
        // B tile load with row guard
        float4 bv = make_float4(0.f, 0.f, 0.f, 0.f);
        int bn = n0 + lr;
        if (bn < N) bv = *(const float4*)(B + (size_t)bn * K + k0 + lc);

        As[lc + 0][lr] = av.x; As[lc + 1][lr] = av.y;
        As[lc + 2][lr] = av.z; As[lc + 3][lr] = av.w;
        Bs[lc + 0][lr] = bv.x; Bs[lc + 1][lr] = bv.y;
        Bs[lc + 2][lr] = bv.z; Bs[lc + 3][lr] = bv.w;
        __syncthreads();

        #pragma unroll
        for (int kk = 0; kk < 16; kk++) {
            float4 a4  = *(const float4*)&As[kk][ty << 2];
            float2 b01 = *(const float2*)&Bs[kk][tx << 2];
            float2 b23 = *(const float2*)&Bs[kk][(tx << 2) + 2];
            unsigned long long B01 = pack2(b01.x, b01.y);
            unsigned long long B23 = pack2(b23.x, b23.y);
            unsigned long long a0 = pack2(a4.x, a4.x);
            unsigned long long a1 = pack2(a4.y, a4.y);
            unsigned long long a2 = pack2(a4.z, a4.z);
            unsigned long long a3 = pack2(a4.w, a4.w);
            ffma2(acc[0][0], a0, B01); ffma2(acc[0][1], a0, B23);
            ffma2(acc[1][0], a1, B01); ffma2(acc[1][1], a1, B23);
            ffma2(acc[2][0], a2, B01); ffma2(acc[2][1], a2, B23);
            ffma2(acc[3][0], a3, B01); ffma2(acc[3][1], a3, B23);
        }
        __syncthreads();
    }

    #pragma unroll
    for (int i = 0; i < 4; i++) {
        int m = m0 + (ty << 2) + i;
        float cs[4];
        unpack2(acc[i][0], cs[0], cs[1]);
        unpack2(acc[i][1], cs[2], cs[3]);
        #pragma unroll
        for (int j = 0; j < 4; j++) {
            int n = n0 + (tx << 2) + j;
            if (n < N) {
                float c = cs[j] + bias[n];
                if (ACT == 1) c = 1.f / (1.f + __expf(-c));
                else if (ACT == 2) c = tanhf(c);
                C[(size_t)m * N + n] = c;
            }
        }
    }
}

// ---------------- row L2-normalize (one warp per row of 256) ----------------
__global__ __launch_bounds__(256)
void normalize_rows(float* __restrict__ X)
{
    int w = (blockIdx.x * blockDim.x + threadIdx.x) >> 5;
    int lane = threadIdx.x & 31;
    if (w >= M_ROWS) return;
    float* row = X + (size_t)w * D_MEM;
    float x[8];
    float ss = 0.f;
    #pragma unroll
    for (int j = 0; j < 8; j++) { x[j] = row[lane + 32 * j]; ss += x[j] * x[j]; }
    #pragma unroll
    for (int o = 16; o; o >>= 1) ss += __shfl_xor_sync(0xffffffffu, ss, o);
    float inv = 1.f / fmaxf(sqrtf(ss), 1e-12f);
    #pragma unroll
    for (int j = 0; j < 8; j++) row[lane + 32 * j] = x[j] * inv;
}

__device__ __forceinline__ float warp_sum(float x) {
    #pragma unroll
    for (int o = 16; o; o >>= 1) x += __shfl_xor_sync(0xffffffffu, x, o);
    return x;
}

// ---------------- gated delta-rule scan ----------------
// Rows of M are independent: M[i,j] <- M[i,j]*lam[i] + beta[i]*(v[i]-read[i])*k[j]
// One warp owns one (batch,row): M-row lives in registers (8 floats/lane,
// column c = lane + 32*j). k_t loads are coalesced & double-buffered.
__global__ __launch_bounds__(128)
void scan_kernel(const float* __restrict__ Kn, const float* __restrict__ V,
                 const float* __restrict__ Beta, const float* __restrict__ Lam,
                 const float* __restrict__ Mem0, float* __restrict__ Sraw,
                 float* __restrict__ MemOut)
{
    const int wid  = threadIdx.x >> 5;
    const int lane = threadIdx.x & 31;
    const int wg = blockIdx.x * 4 + wid;     // 0..511
    const int b = wg >> 8;                   // batch
    const int r = wg & 255;                  // M row

    const float* kb = Kn  + (size_t)b * T_SEQ * D_MEM;
    const float* vb = V   + (size_t)b * T_SEQ * D_MEM + r;
    const float* bb = Beta+ (size_t)b * T_SEQ * D_MEM + r;
    const float* lb = Lam + (size_t)b * T_SEQ * D_MEM + r;

    float m[8];
    #pragma unroll
    for (int j = 0; j < 8; j++)
        m[j] = Mem0[(size_t)b * D_MEM * D_MEM + (size_t)r * D_MEM + lane + 32 * j];

    // prefetch t = 0
    float kk[8], vt, bt, lt;
    #pragma unroll
    for (int j = 0; j < 8; j++) kk[j] = kb[lane + 32 * j];
    vt = vb[0]; bt = bb[0]; lt = lb[0];

    for (int t = 0; t < T_SEQ; t++) {
        // prefetch t+1 (issued early; scoreboard hides latency behind compute)
        float kn[8], vn = 0.f, bn = 0.f, ln = 0.f;
        if (t + 1 < T_SEQ) {
            const float* kp = kb + (size_t)(t + 1) * D_MEM;
            #pragma unroll
            for (int j = 0; j < 8; j++) kn[j] = kp[lane + 32 * j];
            vn = vb[(size_t)(t + 1) * D_MEM];
            bn = bb[(size_t)(t + 1) * D_MEM];
            ln = lb[(size_t)(t + 1) * D_MEM];
        } else {
            #pragma unroll
            for (int j = 0; j < 8; j++) kn[j] = 0.f;
        }

        // read = M . k   (pre-update)
        float s0 = m[0] * kk[0] + m[2] * kk[2];
        float s1 = m[1] * kk[1] + m[3] * kk[3];
        s0 += m[4] * kk[4] + m[6] * kk[6];
        s1 += m[5] * kk[5] + m[7] * kk[7];
        float rd = warp_sum(s0 + s1);

        float corr = (vt - rd) * bt;

        // update + summary dot fused
        float u0 = 0.f, u1 = 0.f;
        #pragma unroll
        for (int j = 0; j < 8; j++) {
            m[j] = m[j] * lt + corr * kk[j];
            if (j & 1) u1 += m[j] * kk[j]; else u0 += m[j] * kk[j];
        }
        float s2 = warp_sum(u0 + u1);

        if (lane == 0)
            Sraw[(size_t)b * T_SEQ * D_MEM + (size_t)t * D_MEM + r] = s2;

        #pragma unroll
        for (int j = 0; j < 8; j++) kk[j] = kn[j];
        vt = vn; bt = bn; lt = ln;
    }

    #pragma unroll
    for (int j = 0; j < 8; j++)
        MemOut[(size_t)b * D_MEM * D_MEM + (size_t)r * D_MEM + lane + 32 * j] = m[j];
}

// ---------------- launch ----------------
extern "C" void kernel_launch(void* const* d_in, const int* in_sizes, int n_in,
                              void* d_out, int out_size)
{
    const float* cf    = (const float*)d_in[0];
    const float* mem0  = (const float*)d_in[1];
    const float* Wk    = (const float*)d_in[2];
    const float* bk    = (const float*)d_in[3];
    const float* Wv    = (const float*)d_in[4];
    const float* bv    = (const float*)d_in[5];
    const float* Wbeta = (const float*)d_in[6];
    const float* bbeta = (const float*)d_in[7];
    const float* Wlam  = (const float*)d_in[8];
    const float* blam  = (const float*)d_in[9];
    const float* Wsum  = (const float*)d_in[10];
    const float* bsum  = (const float*)d_in[11];
    const float* Wlb   = (const float*)d_in[12];
    const float* blb   = (const float*)d_in[13];
    const float* Wph   = (const float*)d_in[14];
    const float* bph   = (const float*)d_in[15];
    const float* Wwin  = (const float*)d_in[16];
    const float* bwin  = (const float*)d_in[17];
    const float* Wmar  = (const float*)d_in[18];
    const float* bmar  = (const float*)d_in[19];

    float* out = (float*)d_out;
    float* out_mem = out + OFF_MEM;
    float* out_sum = out + OFF_SUM;
    float* out_lb  = out + OFF_LB;
    float* out_ph  = out + OFF_PH;
    float* out_win = out + OFF_WIN;
    float* out_mar = out + OFF_MAR;

    float *pk, *pv, *pb, *pl, *ps;
    cudaGetSymbolAddress((void**)&pk, g_k);
    cudaGetSymbolAddress((void**)&pv, g_v);
    cudaGetSymbolAddress((void**)&pb, g_beta);
    cudaGetSymbolAddress((void**)&pl, g_lam);
    cudaGetSymbolAddress((void**)&ps, g_sraw);

    dim3 gproj(D_MEM / 64, M_ROWS / 64);   // (4, 32)
    gemm_bias_act<0><<<gproj, 256>>>(cf, Wk,    bk,    pk, M_ROWS, D_MEM, D_INF);
    gemm_bias_act<0><<<gproj, 256>>>(cf, Wv,    bv,    pv, M_ROWS, D_MEM, D_INF);
    gemm_bias_act<1><<<gproj, 256>>>(cf, Wbeta, bbeta, pb, M_ROWS, D_MEM, D_INF);
    gemm_bias_act<1><<<gproj, 256>>>(cf, Wlam,  blam,  pl, M_ROWS, D_MEM, D_INF);

    normalize_rows<<<256, 256>>>(pk);

    scan_kernel<<<128, 128>>>(pk, pv, pb, pl, mem0, ps, out_mem);

    gemm_bias_act<2><<<dim3(4, 32),   256>>>(ps,      Wsum, bsum, out_sum, M_ROWS, D_MEM,   D_MEM);
    gemm_bias_act<0><<<dim3(500, 32), 256>>>(out_sum, Wlb,  blb,  out_lb,  M_ROWS, VOCAB,   D_MEM);
    gemm_bias_act<0><<<dim3(1, 32),   256>>>(out_sum, Wph,  bph,  out_ph,  M_ROWS, PHASE_N, D_MEM);
    gemm_bias_act<0><<<dim3(500, 32), 256>>>(out_sum, Wwin, bwin, out_win, M_ROWS, VOCAB,   D_MEM);
    gemm_bias_act<0><<<dim3(1, 32),   256>>>(out_sum, Wmar, bmar, out_mar, M_ROWS, MARGIN_N, D_MEM);
}

// round 7
// speedup vs baseline: 2.0104x; 2.0104x over previous
#include <cuda_runtime.h>
#include <cuda_bf16.h>
#include <math.h>
#include <stdint.h>

// Problem constants
#define B_SZ    2
#define T_SEQ   1024
#define D_INF   1024
#define D_MEM   256
#define VOCAB   32000
#define PHASE_N 8
#define MARGIN_N 4
#define M_ROWS  (B_SZ * T_SEQ)   // 2048

// Output layout offsets (float elements)
#define OFF_MEM   0
#define OFF_SUM   131072
#define OFF_LB    655360
#define OFF_PH    66191360
#define OFF_WIN   66207744
#define OFF_MAR   131743744

// Scratch device globals
__device__ float g_k   [M_ROWS * D_MEM];
__device__ float g_v   [M_ROWS * D_MEM];
__device__ float g_beta[M_ROWS * D_MEM];
__device__ float g_lam [M_ROWS * D_MEM];
__device__ float g_sraw[M_ROWS * D_MEM];
// bf16 hi/lo row-major [rows][256]
__device__ __nv_bfloat16 g_A_h [M_ROWS * D_MEM];
__device__ __nv_bfloat16 g_A_l [M_ROWS * D_MEM];
__device__ __nv_bfloat16 g_W1_h[(size_t)VOCAB * D_MEM];
__device__ __nv_bfloat16 g_W1_l[(size_t)VOCAB * D_MEM];
__device__ __nv_bfloat16 g_W2_h[(size_t)VOCAB * D_MEM];
__device__ __nv_bfloat16 g_W2_l[(size_t)VOCAB * D_MEM];

// ===================== helpers =====================
__device__ __forceinline__ uint32_t smem_u32(const void* p) {
    uint32_t a;
    asm("{ .reg .u64 t; cvta.to.shared.u64 t, %1; cvt.u32.u64 %0, t; }" : "=r"(a) : "l"(p));
    return a;
}
__device__ __forceinline__ void cp_async16(uint32_t dst, const void* src) {
    asm volatile("cp.async.cg.shared.global [%0], [%1], 16;" :: "r"(dst), "l"(src));
}
#define CP_COMMIT() asm volatile("cp.async.commit_group;" ::: "memory")
#define CP_WAIT(N)  asm volatile("cp.async.wait_group %0;" :: "n"(N) : "memory")

__device__ __forceinline__ void ldsm4(uint32_t* r, uint32_t addr) {
    asm volatile("ldmatrix.sync.aligned.m8n8.x4.shared.b16 {%0,%1,%2,%3}, [%4];"
        : "=r"(r[0]), "=r"(r[1]), "=r"(r[2]), "=r"(r[3]) : "r"(addr));
}
__device__ __forceinline__ void mma16816(float* c, const uint32_t* a,
                                         uint32_t b0, uint32_t b1) {
    asm volatile(
        "mma.sync.aligned.m16n8k16.row.col.f32.bf16.bf16.f32 "
        "{%0,%1,%2,%3}, {%4,%5,%6,%7}, {%8,%9}, {%0,%1,%2,%3};"
        : "+f"(c[0]), "+f"(c[1]), "+f"(c[2]), "+f"(c[3])
        : "r"(a[0]), "r"(a[1]), "r"(a[2]), "r"(a[3]), "r"(b0), "r"(b1));
}

// packed f32x2 (FFMA2)
__device__ __forceinline__ unsigned long long pack2(float x, float y) {
    unsigned long long r;
    asm("mov.b64 %0, {%1, %2};" : "=l"(r) : "f"(x), "f"(y));
    return r;
}
__device__ __forceinline__ void unpack2(unsigned long long p, float& x, float& y) {
    asm("mov.b64 {%0, %1}, %2;" : "=f"(x), "=f"(y) : "l"(p));
}
__device__ __forceinline__ void ffma2(unsigned long long& d, unsigned long long a,
                                      unsigned long long b) {
    asm("fma.rn.f32x2 %0, %1, %2, %0;" : "+l"(d) : "l"(a), "l"(b));
}

// ===================== generic SIMT GEMM (small heads + summary) =====================
// C[M,N] = A[M,K] @ B[N,K]^T + bias, + act. ACT: 0 none, 1 sigmoid, 2 tanh.
// HILO: also emit bf16 hi/lo of C into row-major [M][N] bf16 arrays.
template <int ACT, bool HILO>
__global__ __launch_bounds__(256)
void gemm_bias_act(const float* __restrict__ A, const float* __restrict__ B,
                   const float* __restrict__ bias, float* __restrict__ C,
                   int M, int N, int K,
                   __nv_bfloat16* __restrict__ gh, __nv_bfloat16* __restrict__ gl)
{
    __shared__ float As[16][68];
    __shared__ float Bs[16][68];

    const int tid = threadIdx.x;
    const int m0 = blockIdx.y * 64;
    const int n0 = blockIdx.x * 64;
    const int ty = tid >> 4;
    const int tx = tid & 15;
    const int lr = tid >> 2;
    const int lc = (tid & 3) << 2;

    unsigned long long acc[4][2];
    #pragma unroll
    for (int i = 0; i < 4; i++) { acc[i][0] = 0ull; acc[i][1] = 0ull; }

    for (int k0 = 0; k0 < K; k0 += 16) {
        float4 av = *(const float4*)(A + (size_t)(m0 + lr) * K + k0 + lc);
        float4 bv = make_float4(0.f, 0.f, 0.f, 0.f);
        int bn = n0 + lr;
        if (bn < N) bv = *(const float4*)(B + (size_t)bn * K + k0 + lc);

        As[lc + 0][lr] = av.x; As[lc + 1][lr] = av.y;
        As[lc + 2][lr] = av.z; As[lc + 3][lr] = av.w;
        Bs[lc + 0][lr] = bv.x; Bs[lc + 1][lr] = bv.y;
        Bs[lc + 2][lr] = bv.z; Bs[lc + 3][lr] = bv.w;
        __syncthreads();

        #pragma unroll
        for (int kk = 0; kk < 16; kk++) {
            float4 a4  = *(const float4*)&As[kk][ty << 2];
            float2 b01 = *(const float2*)&Bs[kk][tx << 2];
            float2 b23 = *(const float2*)&Bs[kk][(tx << 2) + 2];
            unsigned long long B01 = pack2(b01.x, b01.y);
            unsigned long long B23 = pack2(b23.x, b23.y);
            unsigned long long a0 = pack2(a4.x, a4.x);
            unsigned long long a1 = pack2(a4.y, a4.y);
            unsigned long long a2 = pack2(a4.z, a4.z);
            unsigned long long a3 = pack2(a4.w, a4.w);
            ffma2(acc[0][0], a0, B01); ffma2(acc[0][1], a0, B23);
            ffma2(acc[1][0], a1, B01); ffma2(acc[1][1], a1, B23);
            ffma2(acc[2][0], a2, B01); ffma2(acc[2][1], a2, B23);
            ffma2(acc[3][0], a3, B01); ffma2(acc[3][1], a3, B23);
        }
        __syncthreads();
    }

    #pragma unroll
    for (int i = 0; i < 4; i++) {
        int m = m0 + (ty << 2) + i;
        float cs[4];
        unpack2(acc[i][0], cs[0], cs[1]);
        unpack2(acc[i][1], cs[2], cs[3]);
        #pragma unroll
        for (int j = 0; j < 4; j++) {
            int n = n0 + (tx << 2) + j;
            if (n < N) {
                float c = cs[j] + bias[n];
                if (ACT == 1) c = 1.f / (1.f + __expf(-c));
                else if (ACT == 2) c = tanhf(c);
                cs[j] = c;
                C[(size_t)m * N + n] = c;
            }
        }
        if (HILO) {
            int nb = n0 + (tx << 2);
            __nv_bfloat16 h0 = __float2bfloat16(cs[0]);
            __nv_bfloat16 h1 = __float2bfloat16(cs[1]);
            __nv_bfloat16 h2 = __float2bfloat16(cs[2]);
            __nv_bfloat16 h3 = __float2bfloat16(cs[3]);
            __nv_bfloat16 l0 = __float2bfloat16(cs[0] - __bfloat162float(h0));
            __nv_bfloat16 l1 = __float2bfloat16(cs[1] - __bfloat162float(h1));
            __nv_bfloat16 l2 = __float2bfloat16(cs[2] - __bfloat162float(h2));
            __nv_bfloat16 l3 = __float2bfloat16(cs[3] - __bfloat162float(h3));
            __nv_bfloat162* ph = (__nv_bfloat162*)(gh + (size_t)m * 256 + nb);
            __nv_bfloat162* pl = (__nv_bfloat162*)(gl + (size_t)m * 256 + nb);
            ph[0] = __halves2bfloat162(h0, h1);
            ph[1] = __halves2bfloat162(h2, h3);
            pl[0] = __halves2bfloat162(l0, l1);
            pl[1] = __halves2bfloat162(l2, l3);
        }
    }
}

// ===================== merged projections (grid.z selects head) =====================
__global__ __launch_bounds__(256)
void proj_gemm(const float* __restrict__ A,
               const float* __restrict__ W0, const float* __restrict__ W1,
               const float* __restrict__ W2, const float* __restrict__ W3,
               const float* __restrict__ b0, const float* __restrict__ b1,
               const float* __restrict__ b2, const float* __restrict__ b3,
               float* __restrict__ C0, float* __restrict__ C1,
               float* __restrict__ C2, float* __restrict__ C3)
{
    const int z = blockIdx.z;
    const float* B; const float* bias; float* C; int act;
    switch (z) {
        case 0:  B = W0; bias = b0; C = C0; act = 0; break;
        case 1:  B = W1; bias = b1; C = C1; act = 0; break;
        case 2:  B = W2; bias = b2; C = C2; act = 1; break;
        default: B = W3; bias = b3; C = C3; act = 1; break;
    }
    const int K = D_INF, N = D_MEM;

    __shared__ float As[16][68];
    __shared__ float Bs[16][68];

    const int tid = threadIdx.x;
    const int m0 = blockIdx.y * 64;
    const int n0 = blockIdx.x * 64;
    const int ty = tid >> 4;
    const int tx = tid & 15;
    const int lr = tid >> 2;
    const int lc = (tid & 3) << 2;

    unsigned long long acc[4][2];
    #pragma unroll
    for (int i = 0; i < 4; i++) { acc[i][0] = 0ull; acc[i][1] = 0ull; }

    for (int k0 = 0; k0 < K; k0 += 16) {
        float4 av = *(const float4*)(A + (size_t)(m0 + lr) * K + k0 + lc);
        float4 bv = *(const float4*)(B + (size_t)(n0 + lr) * K + k0 + lc);
        As[lc + 0][lr] = av.x; As[lc + 1][lr] = av.y;
        As[lc + 2][lr] = av.z; As[lc + 3][lr] = av.w;
        Bs[lc + 0][lr] = bv.x; Bs[lc + 1][lr] = bv.y;
        Bs[lc + 2][lr] = bv.z; Bs[lc + 3][lr] = bv.w;
        __syncthreads();
        #pragma unroll
        for (int kk = 0; kk < 16; kk++) {
            float4 a4  = *(const float4*)&As[kk][ty << 2];
            float2 b01 = *(const float2*)&Bs[kk][tx << 2];
            float2 b23 = *(const float2*)&Bs[kk][(tx << 2) + 2];
            unsigned long long B01 = pack2(b01.x, b01.y);
            unsigned long long B23 = pack2(b23.x, b23.y);
            unsigned long long a0 = pack2(a4.x, a4.x);
            unsigned long long a1 = pack2(a4.y, a4.y);
            unsigned long long a2 = pack2(a4.z, a4.z);
            unsigned long long a3 = pack2(a4.w, a4.w);
            ffma2(acc[0][0], a0, B01); ffma2(acc[0][1], a0, B23);
            ffma2(acc[1][0], a1, B01); ffma2(acc[1][1], a1, B23);
            ffma2(acc[2][0], a2, B01); ffma2(acc[2][1], a2, B23);
            ffma2(acc[3][0], a3, B01); ffma2(acc[3][1], a3, B23);
        }
        __syncthreads();
    }

    #pragma unroll
    for (int i = 0; i < 4; i++) {
        int m = m0 + (ty << 2) + i;
        float cs[4];
        unpack2(acc[i][0], cs[0], cs[1]);
        unpack2(acc[i][1], cs[2], cs[3]);
        #pragma unroll
        for (int j = 0; j < 4; j++) {
            int n = n0 + (tx << 2) + j;
            float c = cs[j] + bias[n];
            if (act == 1) c = 1.f / (1.f + __expf(-c));
            C[(size_t)m * N + n] = c;
        }
    }
}

// ===================== weight bf16 hi/lo pre-convert (row-major) ==============
__global__ __launch_bounds__(256)
void convert_w(const float* __restrict__ W,
               __nv_bfloat16* __restrict__ oh, __nv_bfloat16* __restrict__ ol)
{
    int i = blockIdx.x * 256 + threadIdx.x;     // [0, 32000*64)
    int n  = i >> 6;
    int kq = (i & 63) << 2;
    float4 w = *(const float4*)(W + (size_t)n * 256 + kq);
    size_t o = (size_t)n * 256 + kq;

    __nv_bfloat16 h0 = __float2bfloat16(w.x);
    __nv_bfloat16 h1 = __float2bfloat16(w.y);
    __nv_bfloat16 h2 = __float2bfloat16(w.z);
    __nv_bfloat16 h3 = __float2bfloat16(w.w);
    __nv_bfloat16 l0 = __float2bfloat16(w.x - __bfloat162float(h0));
    __nv_bfloat16 l1 = __float2bfloat16(w.y - __bfloat162float(h1));
    __nv_bfloat16 l2 = __float2bfloat16(w.z - __bfloat162float(h2));
    __nv_bfloat16 l3 = __float2bfloat16(w.w - __bfloat162float(h3));
    ((__nv_bfloat162*)(oh + o))[0] = __halves2bfloat162(h0, h1);
    ((__nv_bfloat162*)(oh + o))[1] = __halves2bfloat162(h2, h3);
    ((__nv_bfloat162*)(ol + o))[0] = __halves2bfloat162(l0, l1);
    ((__nv_bfloat162*)(ol + o))[1] = __halves2bfloat162(l2, l3);
}

// ===================== mma.sync vocab GEMM =====================
// C[2048,32000] = A[2048,256] @ B[32000,256]^T + bias
// bf16 3-term split: AhBh + AlBh + AhBl, fp32 accumulate.
// CTA 128x128, BK=32, 8 warps (2x4), warp tile 64x32, cp.async double buffer.
#define VK_PAD   40                       // bf16 row stride in SMEM
#define VK_TILE  (128 * VK_PAD * 2)       // 10240 bytes per tile
#define VK_STAGE (4 * VK_TILE)            // Ah, Al, Bh, Bl = 40960 bytes
#define VK_SMEM  (2 * VK_STAGE)           // 81920

__global__ __launch_bounds__(256, 2)
void vocab_mma(const __nv_bfloat16* __restrict__ gAh, const __nv_bfloat16* __restrict__ gAl,
               const __nv_bfloat16* __restrict__ gBh, const __nv_bfloat16* __restrict__ gBl,
               const float* __restrict__ bias, float* __restrict__ C)
{
    extern __shared__ __align__(16) char smem_raw[];
    const int tid  = threadIdx.x;
    const int warp = tid >> 5, lane = tid & 31;
    const int wm = warp >> 2, wn = warp & 3;        // 2 x 4 warp grid
    const int m0 = blockIdx.y * 128, n0 = blockIdx.x * 128;

    const uint32_t sbase = smem_u32(smem_raw);

    // loader mapping: per tile, thread handles row=tid/2, 32B half tid&1
    const int lrow = tid >> 1;
    const int lhal = tid & 1;

    float acc[4][4][4];
    #pragma unroll
    for (int i = 0; i < 4; i++)
        #pragma unroll
        for (int j = 0; j < 4; j++) {
            acc[i][j][0] = 0.f; acc[i][j][1] = 0.f;
            acc[i][j][2] = 0.f; acc[i][j][3] = 0.f;
        }

    auto issue_stage = [&](int kc) {
        const uint32_t st = sbase + (kc & 1) * VK_STAGE;
        const size_t gA = (size_t)(m0 + lrow) * 256 + kc * 32 + lhal * 16;
        const size_t gB = (size_t)(n0 + lrow) * 256 + kc * 32 + lhal * 16;
        const uint32_t sd = st + lrow * (VK_PAD * 2) + lhal * 32;
        cp_async16(sd + 0 * VK_TILE,      gAh + gA);
        cp_async16(sd + 0 * VK_TILE + 16, gAh + gA + 8);
        cp_async16(sd + 1 * VK_TILE,      gAl + gA);
        cp_async16(sd + 1 * VK_TILE + 16, gAl + gA + 8);
        cp_async16(sd + 2 * VK_TILE,      gBh + gB);
        cp_async16(sd + 2 * VK_TILE + 16, gBh + gB + 8);
        cp_async16(sd + 3 * VK_TILE,      gBl + gB);
        cp_async16(sd + 3 * VK_TILE + 16, gBl + gB + 8);
    };

    issue_stage(0);
    CP_COMMIT();

    for (int kc = 0; kc < 8; kc++) {
        if (kc < 7) { issue_stage(kc + 1); CP_COMMIT(); CP_WAIT(1); }
        else        { CP_WAIT(0); }
        __syncthreads();

        const uint32_t st = sbase + (kc & 1) * VK_STAGE;
        const uint32_t tAh = st;
        const uint32_t tAl = st + VK_TILE;
        const uint32_t tBh = st + 2 * VK_TILE;
        const uint32_t tBl = st + 3 * VK_TILE;

        // per-lane ldmatrix address components
        const uint32_t ar = wm * 64 + (lane & 15);          // + fm*16
        const uint32_t ac16 = (lane >> 4) * 8;              // + h*16
        const int g = lane >> 3, r8 = lane & 7;
        const uint32_t br = wn * 32 + ((g >> 1) * 8) + r8;  // + p*16
        const uint32_t bc = (g & 1) * 8;                    // + h*16

        #pragma unroll
        for (int h = 0; h < 2; h++) {
            uint32_t a[4][4], bh[2][4], bl[2][4];
            #pragma unroll
            for (int fm = 0; fm < 4; fm++)
                ldsm4(a[fm], tAh + ((ar + fm * 16) * VK_PAD + ac16 + h * 16) * 2);
            #pragma unroll
            for (int p = 0; p < 2; p++) {
                ldsm4(bh[p], tBh + ((br + p * 16) * VK_PAD + bc + h * 16) * 2);
                ldsm4(bl[p], tBl + ((br + p * 16) * VK_PAD + bc + h * 16) * 2);
            }
            // Ah*Bh and Ah*Bl
            #pragma unroll
            for (int fm = 0; fm < 4; fm++)
                #pragma unroll
                for (int fn = 0; fn < 4; fn++) {
                    const int p = fn >> 1, q = fn & 1;
                    mma16816(acc[fm][fn], a[fm], bh[p][q * 2], bh[p][q * 2 + 1]);
                    mma16816(acc[fm][fn], a[fm], bl[p][q * 2], bl[p][q * 2 + 1]);
                }
            // Al*Bh (reload A frags as lo)
            #pragma unroll
            for (int fm = 0; fm < 4; fm++)
                ldsm4(a[fm], tAl + ((ar + fm * 16) * VK_PAD + ac16 + h * 16) * 2);
            #pragma unroll
            for (int fm = 0; fm < 4; fm++)
                #pragma unroll
                for (int fn = 0; fn < 4; fn++) {
                    const int p = fn >> 1, q = fn & 1;
                    mma16816(acc[fm][fn], a[fm], bh[p][q * 2], bh[p][q * 2 + 1]);
                }
        }
        __syncthreads();
    }

    // epilogue: direct float2 stores with bias
    float2 bv[4];
    #pragma unroll
    for (int fn = 0; fn < 4; fn++)
        bv[fn] = *(const float2*)(bias + n0 + wn * 32 + fn * 8 + (lane & 3) * 2);

    #pragma unroll
    for (int fm = 0; fm < 4; fm++) {
        const int r0 = m0 + wm * 64 + fm * 16 + (lane >> 2);
        #pragma unroll
        for (int fn = 0; fn < 4; fn++) {
            const int col = n0 + wn * 32 + fn * 8 + (lane & 3) * 2;
            float2 v0 = make_float2(acc[fm][fn][0] + bv[fn].x, acc[fm][fn][1] + bv[fn].y);
            float2 v1 = make_float2(acc[fm][fn][2] + bv[fn].x, acc[fm][fn][3] + bv[fn].y);
            *(float2*)(C + (size_t)r0 * VOCAB + col)       = v0;
            *(float2*)(C + (size_t)(r0 + 8) * VOCAB + col) = v1;
        }
    }
}

// ===================== row L2-normalize =====================
__global__ __launch_bounds__(256)
void normalize_rows(float* __restrict__ X)
{
    int w = (blockIdx.x * blockDim.x + threadIdx.x) >> 5;
    int lane = threadIdx.x & 31;
    if (w >= M_ROWS) return;
    float* row = X + (size_t)w * D_MEM;
    float x[8];
    float ss = 0.f;
    #pragma unroll
    for (int j = 0; j < 8; j++) { x[j] = row[lane + 32 * j]; ss += x[j] * x[j]; }
    #pragma unroll
    for (int o = 16; o; o >>= 1) ss += __shfl_xor_sync(0xffffffffu, ss, o);
    float inv = 1.f / fmaxf(sqrtf(ss), 1e-12f);
    #pragma unroll
    for (int j = 0; j < 8; j++) row[lane + 32 * j] = x[j] * inv;
}

__device__ __forceinline__ float warp_sum(float x) {
    #pragma unroll
    for (int o = 16; o; o >>= 1) x += __shfl_xor_sync(0xffffffffu, x, o);
    return x;
}

// ===================== gated delta-rule scan =====================
// ||k||=1  =>  summary_raw = lam*read + corr  (no second reduction needed)
__global__ __launch_bounds__(128)
void scan_kernel(const float* __restrict__ Kn, const float* __restrict__ V,
                 const float* __restrict__ Beta, const float* __restrict__ Lam,
                 const float* __restrict__ Mem0, float* __restrict__ Sraw,
                 float* __restrict__ MemOut)
{
    const int wid  = threadIdx.x >> 5;
    const int lane = threadIdx.x & 31;
    const int wg = blockIdx.x * 4 + wid;
    const int b = wg >> 8;
    const int r = wg & 255;

    const float* kb = Kn  + (size_t)b * T_SEQ * D_MEM;
    const float* vb = V   + (size_t)b * T_SEQ * D_MEM + r;
    const float* bb = Beta+ (size_t)b * T_SEQ * D_MEM + r;
    const float* lb = Lam + (size_t)b * T_SEQ * D_MEM + r;

    float m[8];
    #pragma unroll
    for (int j = 0; j < 8; j++)
        m[j] = Mem0[(size_t)b * D_MEM * D_MEM + (size_t)r * D_MEM + lane + 32 * j];

    float kk[8], vt, bt, lt;
    #pragma unroll
    for (int j = 0; j < 8; j++) kk[j] = kb[lane + 32 * j];
    vt = vb[0]; bt = bb[0]; lt = lb[0];

    for (int t = 0; t < T_SEQ; t++) {
        float kn[8], vn = 0.f, bn = 0.f, ln = 0.f;
        if (t + 1 < T_SEQ) {
            const float* kp = kb + (size_t)(t + 1) * D_MEM;
            #pragma unroll
            for (int j = 0; j < 8; j++) kn[j] = kp[lane + 32 * j];
            vn = vb[(size_t)(t + 1) * D_MEM];
            bn = bb[(size_t)(t + 1) * D_MEM];
            ln = lb[(size_t)(t + 1) * D_MEM];
        } else {
            #pragma unroll
            for (int j = 0; j < 8; j++) kn[j] = 0.f;
        }

        float s0 = m[0] * kk[0] + m[2] * kk[2];
        float s1 = m[1] * kk[1] + m[3] * kk[3];
        s0 += m[4] * kk[4] + m[6] * kk[6];
        s1 += m[5] * kk[5] + m[7] * kk[7];
        float rd = warp_sum(s0 + s1);

        float corr = (vt - rd) * bt;
        float s2 = lt * rd + corr;

        if (lane == 0)
            Sraw[(size_t)b * T_SEQ * D_MEM + (size_t)t * D_MEM + r] = s2;

        #pragma unroll
        for (int j = 0; j < 8; j++) {
            m[j] = m[j] * lt + corr * kk[j];
            kk[j] = kn[j];
        }
        vt = vn; bt = bn; lt = ln;
    }

    #pragma unroll
    for (int j = 0; j < 8; j++)
        MemOut[(size_t)b * D_MEM * D_MEM + (size_t)r * D_MEM + lane + 32 * j] = m[j];
}

// ===================== launch =====================
extern "C" void kernel_launch(void* const* d_in, const int* in_sizes, int n_in,
                              void* d_out, int out_size)
{
    const float* cf    = (const float*)d_in[0];
    const float* mem0  = (const float*)d_in[1];
    const float* Wk    = (const float*)d_in[2];
    const float* bk    = (const float*)d_in[3];
    const float* Wv    = (const float*)d_in[4];
    const float* bv    = (const float*)d_in[5];
    const float* Wbeta = (const float*)d_in[6];
    const float* bbeta = (const float*)d_in[7];
    const float* Wlam  = (const float*)d_in[8];
    const float* blam  = (const float*)d_in[9];
    const float* Wsum  = (const float*)d_in[10];
    const float* bsum  = (const float*)d_in[11];
    const float* Wlb   = (const float*)d_in[12];
    const float* blb   = (const float*)d_in[13];
    const float* Wph   = (const float*)d_in[14];
    const float* bph   = (const float*)d_in[15];
    const float* Wwin  = (const float*)d_in[16];
    const float* bwin  = (const float*)d_in[17];
    const float* Wmar  = (const float*)d_in[18];
    const float* bmar  = (const float*)d_in[19];

    float* out = (float*)d_out;
    float* out_mem = out + OFF_MEM;
    float* out_sum = out + OFF_SUM;
    float* out_lb  = out + OFF_LB;
    float* out_ph  = out + OFF_PH;
    float* out_win = out + OFF_WIN;
    float* out_mar = out + OFF_MAR;

    float *pk, *pv, *pb, *pl, *ps;
    __nv_bfloat16 *pAh, *pAl, *pW1h, *pW1l, *pW2h, *pW2l;
    cudaGetSymbolAddress((void**)&pk, g_k);
    cudaGetSymbolAddress((void**)&pv, g_v);
    cudaGetSymbolAddress((void**)&pb, g_beta);
    cudaGetSymbolAddress((void**)&pl, g_lam);
    cudaGetSymbolAddress((void**)&ps, g_sraw);
    cudaGetSymbolAddress((void**)&pAh, g_A_h);
    cudaGetSymbolAddress((void**)&pAl, g_A_l);
    cudaGetSymbolAddress((void**)&pW1h, g_W1_h);
    cudaGetSymbolAddress((void**)&pW1l, g_W1_l);
    cudaGetSymbolAddress((void**)&pW2h, g_W2_h);
    cudaGetSymbolAddress((void**)&pW2l, g_W2_l);

    cudaFuncSetAttribute(vocab_mma, cudaFuncAttributeMaxDynamicSharedMemorySize, VK_SMEM);

    // weight pre-convert (independent of the recurrence path)
    convert_w<<<8000, 256>>>(Wlb,  pW1h, pW1l);
    convert_w<<<8000, 256>>>(Wwin, pW2h, pW2l);

    // projections (merged)
    proj_gemm<<<dim3(4, 32, 4), 256>>>(cf, Wk, Wv, Wbeta, Wlam,
                                       bk, bv, bbeta, blam,
                                       pk, pv, pb, pl);

    normalize_rows<<<256, 256>>>(pk);

    scan_kernel<<<128, 128>>>(pk, pv, pb, pl, mem0, ps, out_mem);

    // summary GEMM (tanh) + bf16 hi/lo side outputs
    gemm_bias_act<2, true><<<dim3(4, 32), 256>>>(ps, Wsum, bsum, out_sum,
                                                 M_ROWS, D_MEM, D_MEM, pAh, pAl);

    // vocab GEMMs on tensor cores (mma.sync bf16, 3-term split)
    vocab_mma<<<dim3(250, 16), 256, VK_SMEM>>>(pAh, pAl, pW1h, pW1l, blb,  out_lb);
    vocab_mma<<<dim3(250, 16), 256, VK_SMEM>>>(pAh, pAl, pW2h, pW2l, bwin, out_win);

    // small heads
    gemm_bias_act<0, false><<<dim3(1, 32), 256>>>(out_sum, Wph,  bph,  out_ph,
                                                  M_ROWS, PHASE_N, D_MEM, nullptr, nullptr);
    gemm_bias_act<0, false><<<dim3(1, 32), 256>>>(out_sum, Wmar, bmar, out_mar,
                                                  M_ROWS, MARGIN_N, D_MEM, nullptr, nullptr);
}

// round 8
// speedup vs baseline: 2.3469x; 1.1674x over previous
#include <cuda_runtime.h>
#include <cuda_fp16.h>
#include <math.h>
#include <stdint.h>

// Problem constants
#define B_SZ    2
#define T_SEQ   1024
#define D_INF   1024
#define D_MEM   256
#define VOCAB   32000
#define PHASE_N 8
#define MARGIN_N 4
#define M_ROWS  (B_SZ * T_SEQ)   // 2048

// Output layout offsets (float elements)
#define OFF_MEM   0
#define OFF_SUM   131072
#define OFF_LB    655360
#define OFF_PH    66191360
#define OFF_WIN   66207744
#define OFF_MAR   131743744

// Scratch device globals
__device__ float g_k   [M_ROWS * D_MEM];
__device__ float g_v   [M_ROWS * D_MEM];
__device__ float g_beta[M_ROWS * D_MEM];
__device__ float g_lam [M_ROWS * D_MEM];
__device__ float g_sraw[M_ROWS * D_MEM];
// fp16 operands for the vocab GEMMs
__device__ __half g_A_h [M_ROWS * D_MEM];          // summary hi
__device__ __half g_A_l [M_ROWS * D_MEM];          // summary lo (residual)
__device__ __half g_W1f [(size_t)VOCAB * D_MEM];   // fp16(Wlb)
__device__ __half g_W2f [(size_t)VOCAB * D_MEM];   // fp16(Wwin)

// ===================== helpers =====================
__device__ __forceinline__ uint32_t smem_u32(const void* p) {
    uint32_t a;
    asm("{ .reg .u64 t; cvta.to.shared.u64 t, %1; cvt.u32.u64 %0, t; }" : "=r"(a) : "l"(p));
    return a;
}
__device__ __forceinline__ void cp_async16(uint32_t dst, const void* src) {
    asm volatile("cp.async.cg.shared.global [%0], [%1], 16;" :: "r"(dst), "l"(src));
}
#define CP_COMMIT() asm volatile("cp.async.commit_group;" ::: "memory")
#define CP_WAIT(N)  asm volatile("cp.async.wait_group %0;" :: "n"(N) : "memory")

__device__ __forceinline__ void ldsm4(uint32_t* r, uint32_t addr) {
    asm volatile("ldmatrix.sync.aligned.m8n8.x4.shared.b16 {%0,%1,%2,%3}, [%4];"
        : "=r"(r[0]), "=r"(r[1]), "=r"(r[2]), "=r"(r[3]) : "r"(addr));
}
__device__ __forceinline__ void mma16816h(float* c, const uint32_t* a,
                                          uint32_t b0, uint32_t b1) {
    asm volatile(
        "mma.sync.aligned.m16n8k16.row.col.f32.f16.f16.f32 "
        "{%0,%1,%2,%3}, {%4,%5,%6,%7}, {%8,%9}, {%0,%1,%2,%3};"
        : "+f"(c[0]), "+f"(c[1]), "+f"(c[2]), "+f"(c[3])
        : "r"(a[0]), "r"(a[1]), "r"(a[2]), "r"(a[3]), "r"(b0), "r"(b1));
}

// packed f32x2 (FFMA2)
__device__ __forceinline__ unsigned long long pack2(float x, float y) {
    unsigned long long r;
    asm("mov.b64 %0, {%1, %2};" : "=l"(r) : "f"(x), "f"(y));
    return r;
}
__device__ __forceinline__ void unpack2(unsigned long long p, float& x, float& y) {
    asm("mov.b64 {%0, %1}, %2;" : "=f"(x), "=f"(y) : "l"(p));
}
__device__ __forceinline__ void ffma2(unsigned long long& d, unsigned long long a,
                                      unsigned long long b) {
    asm("fma.rn.f32x2 %0, %1, %2, %0;" : "+l"(d) : "l"(a), "l"(b));
}

// ===================== generic SIMT GEMM (small heads + summary) =====================
// C[M,N] = A[M,K] @ B[N,K]^T + bias, + act. ACT: 0 none, 1 sigmoid, 2 tanh.
// HILO: also emit fp16 hi/lo of C into row-major [M][N] half arrays.
template <int ACT, bool HILO>
__global__ __launch_bounds__(256)
void gemm_bias_act(const float* __restrict__ A, const float* __restrict__ B,
                   const float* __restrict__ bias, float* __restrict__ C,
                   int M, int N, int K,
                   __half* __restrict__ gh, __half* __restrict__ gl)
{
    __shared__ float As[16][68];
    __shared__ float Bs[16][68];

    const int tid = threadIdx.x;
    const int m0 = blockIdx.y * 64;
    const int n0 = blockIdx.x * 64;
    const int ty = tid >> 4;
    const int tx = tid & 15;
    const int lr = tid >> 2;
    const int lc = (tid & 3) << 2;

    unsigned long long acc[4][2];
    #pragma unroll
    for (int i = 0; i < 4; i++) { acc[i][0] = 0ull; acc[i][1] = 0ull; }

    for (int k0 = 0; k0 < K; k0 += 16) {
        float4 av = *(const float4*)(A + (size_t)(m0 + lr) * K + k0 + lc);
        float4 bv = make_float4(0.f, 0.f, 0.f, 0.f);
        int bn = n0 + lr;
        if (bn < N) bv = *(const float4*)(B + (size_t)bn * K + k0 + lc);

        As[lc + 0][lr] = av.x; As[lc + 1][lr] = av.y;
        As[lc + 2][lr] = av.z; As[lc + 3][lr] = av.w;
        Bs[lc + 0][lr] = bv.x; Bs[lc + 1][lr] = bv.y;
        Bs[lc + 2][lr] = bv.z; Bs[lc + 3][lr] = bv.w;
        __syncthreads();

        #pragma unroll
        for (int kk = 0; kk < 16; kk++) {
            float4 a4  = *(const float4*)&As[kk][ty << 2];
            float2 b01 = *(const float2*)&Bs[kk][tx << 2];
            float2 b23 = *(const float2*)&Bs[kk][(tx << 2) + 2];
            unsigned long long B01 = pack2(b01.x, b01.y);
            unsigned long long B23 = pack2(b23.x, b23.y);
            unsigned long long a0 = pack2(a4.x, a4.x);
            unsigned long long a1 = pack2(a4.y, a4.y);
            unsigned long long a2 = pack2(a4.z, a4.z);
            unsigned long long a3 = pack2(a4.w, a4.w);
            ffma2(acc[0][0], a0, B01); ffma2(acc[0][1], a0, B23);
            ffma2(acc[1][0], a1, B01); ffma2(acc[1][1], a1, B23);
            ffma2(acc[2][0], a2, B01); ffma2(acc[2][1], a2, B23);
            ffma2(acc[3][0], a3, B01); ffma2(acc[3][1], a3, B23);
        }
        __syncthreads();
    }

    #pragma unroll
    for (int i = 0; i < 4; i++) {
        int m = m0 + (ty << 2) + i;
        float cs[4];
        unpack2(acc[i][0], cs[0], cs[1]);
        unpack2(acc[i][1], cs[2], cs[3]);
        #pragma unroll
        for (int j = 0; j < 4; j++) {
            int n = n0 + (tx << 2) + j;
            if (n < N) {
                float c = cs[j] + bias[n];
                if (ACT == 1) c = 1.f / (1.f + __expf(-c));
                else if (ACT == 2) c = tanhf(c);
                cs[j] = c;
                C[(size_t)m * N + n] = c;
            }
        }
        if (HILO) {
            int nb = n0 + (tx << 2);
            __half h0 = __float2half_rn(cs[0]);
            __half h1 = __float2half_rn(cs[1]);
            __half h2 = __float2half_rn(cs[2]);
            __half h3 = __float2half_rn(cs[3]);
            __half l0 = __float2half_rn(cs[0] - __half2float(h0));
            __half l1 = __float2half_rn(cs[1] - __half2float(h1));
            __half l2 = __float2half_rn(cs[2] - __half2float(h2));
            __half l3 = __float2half_rn(cs[3] - __half2float(h3));
            __half2* ph = (__half2*)(gh + (size_t)m * 256 + nb);
            __half2* pl = (__half2*)(gl + (size_t)m * 256 + nb);
            ph[0] = __halves2half2(h0, h1);
            ph[1] = __halves2half2(h2, h3);
            pl[0] = __halves2half2(l0, l1);
            pl[1] = __halves2half2(l2, l3);
        }
    }
}

// ===================== merged projections (grid.z selects head) =====================
__global__ __launch_bounds__(256)
void proj_gemm(const float* __restrict__ A,
               const float* __restrict__ W0, const float* __restrict__ W1,
               const float* __restrict__ W2, const float* __restrict__ W3,
               const float* __restrict__ b0, const float* __restrict__ b1,
               const float* __restrict__ b2, const float* __restrict__ b3,
               float* __restrict__ C0, float* __restrict__ C1,
               float* __restrict__ C2, float* __restrict__ C3)
{
    const int z = blockIdx.z;
    const float* B; const float* bias; float* C; int act;
    switch (z) {
        case 0:  B = W0; bias = b0; C = C0; act = 0; break;
        case 1:  B = W1; bias = b1; C = C1; act = 0; break;
        case 2:  B = W2; bias = b2; C = C2; act = 1; break;
        default: B = W3; bias = b3; C = C3; act = 1; break;
    }
    const int K = D_INF, N = D_MEM;

    __shared__ float As[16][68];
    __shared__ float Bs[16][68];

    const int tid = threadIdx.x;
    const int m0 = blockIdx.y * 64;
    const int n0 = blockIdx.x * 64;
    const int ty = tid >> 4;
    const int tx = tid & 15;
    const int lr = tid >> 2;
    const int lc = (tid & 3) << 2;

    unsigned long long acc[4][2];
    #pragma unroll
    for (int i = 0; i < 4; i++) { acc[i][0] = 0ull; acc[i][1] = 0ull; }

    for (int k0 = 0; k0 < K; k0 += 16) {
        float4 av = *(const float4*)(A + (size_t)(m0 + lr) * K + k0 + lc);
        float4 bv = *(const float4*)(B + (size_t)(n0 + lr) * K + k0 + lc);
        As[lc + 0][lr] = av.x; As[lc + 1][lr] = av.y;
        As[lc + 2][lr] = av.z; As[lc + 3][lr] = av.w;
        Bs[lc + 0][lr] = bv.x; Bs[lc + 1][lr] = bv.y;
        Bs[lc + 2][lr] = bv.z; Bs[lc + 3][lr] = bv.w;
        __syncthreads();
        #pragma unroll
        for (int kk = 0; kk < 16; kk++) {
            float4 a4  = *(const float4*)&As[kk][ty << 2];
            float2 b01 = *(const float2*)&Bs[kk][tx << 2];
            float2 b23 = *(const float2*)&Bs[kk][(tx << 2) + 2];
            unsigned long long B01 = pack2(b01.x, b01.y);
            unsigned long long B23 = pack2(b23.x, b23.y);
            unsigned long long a0 = pack2(a4.x, a4.x);
            unsigned long long a1 = pack2(a4.y, a4.y);
            unsigned long long a2 = pack2(a4.z, a4.z);
            unsigned long long a3 = pack2(a4.w, a4.w);
            ffma2(acc[0][0], a0, B01); ffma2(acc[0][1], a0, B23);
            ffma2(acc[1][0], a1, B01); ffma2(acc[1][1], a1, B23);
            ffma2(acc[2][0], a2, B01); ffma2(acc[2][1], a2, B23);
            ffma2(acc[3][0], a3, B01); ffma2(acc[3][1], a3, B23);
        }
        __syncthreads();
    }

    #pragma unroll
    for (int i = 0; i < 4; i++) {
        int m = m0 + (ty << 2) + i;
        float cs[4];
        unpack2(acc[i][0], cs[0], cs[1]);
        unpack2(acc[i][1], cs[2], cs[3]);
        #pragma unroll
        for (int j = 0; j < 4; j++) {
            int n = n0 + (tx << 2) + j;
            float c = cs[j] + bias[n];
            if (act == 1) c = 1.f / (1.f + __expf(-c));
            C[(size_t)m * N + n] = c;
        }
    }
}

// ===================== weight fp16 pre-convert (row-major) ==============
__global__ __launch_bounds__(256)
void convert_w16(const float* __restrict__ W, __half* __restrict__ o)
{
    int i = blockIdx.x * 256 + threadIdx.x;     // [0, 32000*64)
    int n  = i >> 6;
    int kq = (i & 63) << 2;
    float4 w = *(const float4*)(W + (size_t)n * 256 + kq);
    size_t off = (size_t)n * 256 + kq;
    ((__half2*)(o + off))[0] = __halves2half2(__float2half_rn(w.x), __float2half_rn(w.y));
    ((__half2*)(o + off))[1] = __halves2half2(__float2half_rn(w.z), __float2half_rn(w.w));
}

// ===================== mma.sync vocab GEMM (fp16, 2-term) =====================
// C[2048,32000] = A[2048,256] @ B[32000,256]^T + bias
// A split fp16 hi/lo (exact to ~2^-24); B single fp16 (rounding eps ~2^-12).
// C = Ah*B + Al*B. CTA 128x128, BK=32, 8 warps (2x4), 3-stage cp.async pipeline.
#define VK_PAD    40                       // fp16 row stride in SMEM (halfs)
#define VK_TILE   (128 * VK_PAD * 2)       // 10240 bytes per tile
#define VK_STAGE  (3 * VK_TILE)            // Ah, Al, B = 30720 bytes
#define VK_NSTAGE 3
#define VK_SMEM   (VK_NSTAGE * VK_STAGE)   // 92160

__global__ __launch_bounds__(256, 2)
void vocab_mma(const __half* __restrict__ gAh, const __half* __restrict__ gAl,
               const __half* __restrict__ gB,
               const float* __restrict__ bias, float* __restrict__ C)
{
    extern __shared__ __align__(16) char smem_raw[];
    const int tid  = threadIdx.x;
    const int warp = tid >> 5, lane = tid & 31;
    const int wm = warp >> 2, wn = warp & 3;        // 2 x 4 warp grid
    const int m0 = blockIdx.y * 128, n0 = blockIdx.x * 128;

    const uint32_t sbase = smem_u32(smem_raw);

    // loader mapping: per tile, thread handles row=tid/2, 32B half tid&1
    const int lrow = tid >> 1;
    const int lhal = tid & 1;

    float acc[4][4][4];
    #pragma unroll
    for (int i = 0; i < 4; i++)
        #pragma unroll
        for (int j = 0; j < 4; j++) {
            acc[i][j][0] = 0.f; acc[i][j][1] = 0.f;
            acc[i][j][2] = 0.f; acc[i][j][3] = 0.f;
        }

    auto issue_stage = [&](int kc) {
        const uint32_t st = sbase + (kc % VK_NSTAGE) * VK_STAGE;
        const size_t gA = (size_t)(m0 + lrow) * 256 + kc * 32 + lhal * 16;
        const size_t gBo = (size_t)(n0 + lrow) * 256 + kc * 32 + lhal * 16;
        const uint32_t sd = st + lrow * (VK_PAD * 2) + lhal * 32;
        cp_async16(sd + 0 * VK_TILE,      gAh + gA);
        cp_async16(sd + 0 * VK_TILE + 16, gAh + gA + 8);
        cp_async16(sd + 1 * VK_TILE,      gAl + gA);
        cp_async16(sd + 1 * VK_TILE + 16, gAl + gA + 8);
        cp_async16(sd + 2 * VK_TILE,      gB + gBo);
        cp_async16(sd + 2 * VK_TILE + 16, gB + gBo + 8);
    };

    issue_stage(0); CP_COMMIT();
    issue_stage(1); CP_COMMIT();

    // per-lane ldmatrix address components
    const uint32_t ar = wm * 64 + (lane & 15);          // + fm*16
    const uint32_t ac16 = (lane >> 4) * 8;              // + h*16
    const int g = lane >> 3, r8 = lane & 7;
    const uint32_t br = wn * 32 + ((g >> 1) * 8) + r8;  // + p*16
    const uint32_t bc = (g & 1) * 8;                    // + h*16

    #pragma unroll
    for (int kc = 0; kc < 8; kc++) {
        if (kc < 6)      { issue_stage(kc + 2); CP_COMMIT(); CP_WAIT(2); }
        else if (kc == 6){ CP_WAIT(1); }
        else             { CP_WAIT(0); }
        __syncthreads();

        const uint32_t st = sbase + (kc % VK_NSTAGE) * VK_STAGE;
        const uint32_t tAh = st;
        const uint32_t tAl = st + VK_TILE;
        const uint32_t tB  = st + 2 * VK_TILE;

        #pragma unroll
        for (int h = 0; h < 2; h++) {
            uint32_t ah[4][4], al[4][4], b[2][4];
            #pragma unroll
            for (int fm = 0; fm < 4; fm++)
                ldsm4(ah[fm], tAh + ((ar + fm * 16) * VK_PAD + ac16 + h * 16) * 2);
            #pragma unroll
            for (int fm = 0; fm < 4; fm++)
                ldsm4(al[fm], tAl + ((ar + fm * 16) * VK_PAD + ac16 + h * 16) * 2);
            #pragma unroll
            for (int p = 0; p < 2; p++)
                ldsm4(b[p], tB + ((br + p * 16) * VK_PAD + bc + h * 16) * 2);

            #pragma unroll
            for (int fm = 0; fm < 4; fm++)
                #pragma unroll
                for (int fn = 0; fn < 4; fn++) {
                    const int p = fn >> 1, q = fn & 1;
                    mma16816h(acc[fm][fn], ah[fm], b[p][q * 2], b[p][q * 2 + 1]);
                    mma16816h(acc[fm][fn], al[fm], b[p][q * 2], b[p][q * 2 + 1]);
                }
        }
        __syncthreads();
    }

    // epilogue: direct float2 stores with bias
    float2 bv[4];
    #pragma unroll
    for (int fn = 0; fn < 4; fn++)
        bv[fn] = *(const float2*)(bias + n0 + wn * 32 + fn * 8 + (lane & 3) * 2);

    #pragma unroll
    for (int fm = 0; fm < 4; fm++) {
        const int r0 = m0 + wm * 64 + fm * 16 + (lane >> 2);
        #pragma unroll
        for (int fn = 0; fn < 4; fn++) {
            const int col = n0 + wn * 32 + fn * 8 + (lane & 3) * 2;
            float2 v0 = make_float2(acc[fm][fn][0] + bv[fn].x, acc[fm][fn][1] + bv[fn].y);
            float2 v1 = make_float2(acc[fm][fn][2] + bv[fn].x, acc[fm][fn][3] + bv[fn].y);
            *(float2*)(C + (size_t)r0 * VOCAB + col)       = v0;
            *(float2*)(C + (size_t)(r0 + 8) * VOCAB + col) = v1;
        }
    }
}

// ===================== row L2-normalize =====================
__global__ __launch_bounds__(256)
void normalize_rows(float* __restrict__ X)
{
    int w = (blockIdx.x * blockDim.x + threadIdx.x) >> 5;
    int lane = threadIdx.x & 31;
    if (w >= M_ROWS) return;
    float* row = X + (size_t)w * D_MEM;
    float x[8];
    float ss = 0.f;
    #pragma unroll
    for (int j = 0; j < 8; j++) { x[j] = row[lane + 32 * j]; ss += x[j] * x[j]; }
    #pragma unroll
    for (int o = 16; o; o >>= 1) ss += __shfl_xor_sync(0xffffffffu, ss, o);
    float inv = 1.f / fmaxf(sqrtf(ss), 1e-12f);
    #pragma unroll
    for (int j = 0; j < 8; j++) row[lane + 32 * j] = x[j] * inv;
}

__device__ __forceinline__ float warp_sum(float x) {
    #pragma unroll
    for (int o = 16; o; o >>= 1) x += __shfl_xor_sync(0xffffffffu, x, o);
    return x;
}

// ===================== gated delta-rule scan =====================
// ||k||=1  =>  summary_raw = lam*read + corr  (no second reduction needed)
__global__ __launch_bounds__(128)
void scan_kernel(const float* __restrict__ Kn, const float* __restrict__ V,
                 const float* __restrict__ Beta, const float* __restrict__ Lam,
                 const float* __restrict__ Mem0, float* __restrict__ Sraw,
                 float* __restrict__ MemOut)
{
    const int wid  = threadIdx.x >> 5;
    const int lane = threadIdx.x & 31;
    const int wg = blockIdx.x * 4 + wid;
    const int b = wg >> 8;
    const int r = wg & 255;

    const float* kb = Kn  + (size_t)b * T_SEQ * D_MEM;
    const float* vb = V   + (size_t)b * T_SEQ * D_MEM + r;
    const float* bb = Beta+ (size_t)b * T_SEQ * D_MEM + r;
    const float* lb = Lam + (size_t)b * T_SEQ * D_MEM + r;

    float m[8];
    #pragma unroll
    for (int j = 0; j < 8; j++)
        m[j] = Mem0[(size_t)b * D_MEM * D_MEM + (size_t)r * D_MEM + lane + 32 * j];

    float kk[8], vt, bt, lt;
    #pragma unroll
    for (int j = 0; j < 8; j++) kk[j] = kb[lane + 32 * j];
    vt = vb[0]; bt = bb[0]; lt = lb[0];

    for (int t = 0; t < T_SEQ; t++) {
        float kn[8], vn = 0.f, bn = 0.f, ln = 0.f;
        if (t + 1 < T_SEQ) {
            const float* kp = kb + (size_t)(t + 1) * D_MEM;
            #pragma unroll
            for (int j = 0; j < 8; j++) kn[j] = kp[lane + 32 * j];
            vn = vb[(size_t)(t + 1) * D_MEM];
            bn = bb[(size_t)(t + 1) * D_MEM];
            ln = lb[(size_t)(t + 1) * D_MEM];
        } else {
            #pragma unroll
            for (int j = 0; j < 8; j++) kn[j] = 0.f;
        }

        float s0 = m[0] * kk[0] + m[2] * kk[2];
        float s1 = m[1] * kk[1] + m[3] * kk[3];
        s0 += m[4] * kk[4] + m[6] * kk[6];
        s1 += m[5] * kk[5] + m[7] * kk[7];
        float rd = warp_sum(s0 + s1);

        float corr = (vt - rd) * bt;
        float s2 = lt * rd + corr;

        if (lane == 0)
            Sraw[(size_t)b * T_SEQ * D_MEM + (size_t)t * D_MEM + r] = s2;

        #pragma unroll
        for (int j = 0; j < 8; j++) {
            m[j] = m[j] * lt + corr * kk[j];
            kk[j] = kn[j];
        }
        vt = vn; bt = bn; lt = ln;
    }

    #pragma unroll
    for (int j = 0; j < 8; j++)
        MemOut[(size_t)b * D_MEM * D_MEM + (size_t)r * D_MEM + lane + 32 * j] = m[j];
}

// ===================== launch =====================
extern "C" void kernel_launch(void* const* d_in, const int* in_sizes, int n_in,
                              void* d_out, int out_size)
{
    const float* cf    = (const float*)d_in[0];
    const float* mem0  = (const float*)d_in[1];
    const float* Wk    = (const float*)d_in[2];
    const float* bk    = (const float*)d_in[3];
    const float* Wv    = (const float*)d_in[4];
    const float* bv    = (const float*)d_in[5];
    const float* Wbeta = (const float*)d_in[6];
    const float* bbeta = (const float*)d_in[7];
    const float* Wlam  = (const float*)d_in[8];
    const float* blam  = (const float*)d_in[9];
    const float* Wsum  = (const float*)d_in[10];
    const float* bsum  = (const float*)d_in[11];
    const float* Wlb   = (const float*)d_in[12];
    const float* blb   = (const float*)d_in[13];
    const float* Wph   = (const float*)d_in[14];
    const float* bph   = (const float*)d_in[15];
    const float* Wwin  = (const float*)d_in[16];
    const float* bwin  = (const float*)d_in[17];
    const float* Wmar  = (const float*)d_in[18];
    const float* bmar  = (const float*)d_in[19];

    float* out = (float*)d_out;
    float* out_mem = out + OFF_MEM;
    float* out_sum = out + OFF_SUM;
    float* out_lb  = out + OFF_LB;
    float* out_ph  = out + OFF_PH;
    float* out_win = out + OFF_WIN;
    float* out_mar = out + OFF_MAR;

    float *pk, *pv, *pb, *pl, *ps;
    __half *pAh, *pAl, *pW1, *pW2;
    cudaGetSymbolAddress((void**)&pk, g_k);
    cudaGetSymbolAddress((void**)&pv, g_v);
    cudaGetSymbolAddress((void**)&pb, g_beta);
    cudaGetSymbolAddress((void**)&pl, g_lam);
    cudaGetSymbolAddress((void**)&ps, g_sraw);
    cudaGetSymbolAddress((void**)&pAh, g_A_h);
    cudaGetSymbolAddress((void**)&pAl, g_A_l);
    cudaGetSymbolAddress((void**)&pW1, g_W1f);
    cudaGetSymbolAddress((void**)&pW2, g_W2f);

    cudaFuncSetAttribute(vocab_mma, cudaFuncAttributeMaxDynamicSharedMemorySize, VK_SMEM);

    // weight pre-convert (independent of the recurrence path)
    convert_w16<<<8000, 256>>>(Wlb,  pW1);
    convert_w16<<<8000, 256>>>(Wwin, pW2);

    // projections (merged)
    proj_gemm<<<dim3(4, 32, 4), 256>>>(cf, Wk, Wv, Wbeta, Wlam,
                                       bk, bv, bbeta, blam,
                                       pk, pv, pb, pl);

    normalize_rows<<<256, 256>>>(pk);

    scan_kernel<<<128, 128>>>(pk, pv, pb, pl, mem0, ps, out_mem);

    // summary GEMM (tanh) + fp16 hi/lo side outputs
    gemm_bias_act<2, true><<<dim3(4, 32), 256>>>(ps, Wsum, bsum, out_sum,
                                                 M_ROWS, D_MEM, D_MEM, pAh, pAl);

    // vocab GEMMs on tensor cores (mma.sync fp16, 2-term split)
    vocab_mma<<<dim3(250, 16), 256, VK_SMEM>>>(pAh, pAl, pW1, blb,  out_lb);
    vocab_mma<<<dim3(250, 16), 256, VK_SMEM>>>(pAh, pAl, pW2, bwin, out_win);

    // small heads
    gemm_bias_act<0, false><<<dim3(1, 32), 256>>>(out_sum, Wph,  bph,  out_ph,
                                                  M_ROWS, PHASE_N, D_MEM, nullptr, nullptr);
    gemm_bias_act<0, false><<<dim3(1, 32), 256>>>(out_sum, Wmar, bmar, out_mar,
                                                  M_ROWS, MARGIN_N, D_MEM, nullptr, nullptr);
}

// round 10
// speedup vs baseline: 2.7335x; 1.1648x over previous
#include <cuda_runtime.h>
#include <cuda_fp16.h>
#include <math.h>
#include <stdint.h>

// Problem constants
#define B_SZ    2
#define T_SEQ   1024
#define D_INF   1024
#define D_MEM   256
#define VOCAB   32000
#define PHASE_N 8
#define MARGIN_N 4
#define M_ROWS  (B_SZ * T_SEQ)   // 2048

// Output layout offsets (float elements)
#define OFF_MEM   0
#define OFF_SUM   131072
#define OFF_LB    655360
#define OFF_PH    66191360
#define OFF_WIN   66207744
#define OFF_MAR   131743744

// Scratch device globals
__device__ float g_k   [M_ROWS * D_MEM];
__device__ float g_v   [M_ROWS * D_MEM];
__device__ float g_beta[M_ROWS * D_MEM];
__device__ float g_lam [M_ROWS * D_MEM];
__device__ float g_sraw[M_ROWS * D_MEM];
// fp16 operands for the vocab GEMMs
__device__ __half g_A16 [M_ROWS * D_MEM];          // fp16(summary)
__device__ __half g_W1f [(size_t)VOCAB * D_MEM];   // fp16(Wlb)
__device__ __half g_W2f [(size_t)VOCAB * D_MEM];   // fp16(Wwin)

// ===================== helpers =====================
__device__ __forceinline__ uint32_t smem_u32(const void* p) {
    uint32_t a;
    asm("{ .reg .u64 t; cvta.to.shared.u64 t, %1; cvt.u32.u64 %0, t; }" : "=r"(a) : "l"(p));
    return a;
}
__device__ __forceinline__ void cp_async16(uint32_t dst, const void* src) {
    asm volatile("cp.async.cg.shared.global [%0], [%1], 16;" :: "r"(dst), "l"(src));
}
#define CP_COMMIT() asm volatile("cp.async.commit_group;" ::: "memory")
#define CP_WAIT(N)  asm volatile("cp.async.wait_group %0;" :: "n"(N) : "memory")

__device__ __forceinline__ void ldsm4(uint32_t* r, uint32_t addr) {
    asm volatile("ldmatrix.sync.aligned.m8n8.x4.shared.b16 {%0,%1,%2,%3}, [%4];"
        : "=r"(r[0]), "=r"(r[1]), "=r"(r[2]), "=r"(r[3]) : "r"(addr));
}
__device__ __forceinline__ void mma16816h(float* c, const uint32_t* a,
                                          uint32_t b0, uint32_t b1) {
    asm volatile(
        "mma.sync.aligned.m16n8k16.row.col.f32.f16.f16.f32 "
        "{%0,%1,%2,%3}, {%4,%5,%6,%7}, {%8,%9}, {%0,%1,%2,%3};"
        : "+f"(c[0]), "+f"(c[1]), "+f"(c[2]), "+f"(c[3])
        : "r"(a[0]), "r"(a[1]), "r"(a[2]), "r"(a[3]), "r"(b0), "r"(b1));
}

// packed f32x2 (FFMA2)
__device__ __forceinline__ unsigned long long pack2(float x, float y) {
    unsigned long long r;
    asm("mov.b64 %0, {%1, %2};" : "=l"(r) : "f"(x), "f"(y));
    return r;
}
__device__ __forceinline__ void unpack2(unsigned long long p, float& x, float& y) {
    asm("mov.b64 {%0, %1}, %2;" : "=f"(x), "=f"(y) : "l"(p));
}
__device__ __forceinline__ void ffma2(unsigned long long& d, unsigned long long a,
                                      unsigned long long b) {
    asm("fma.rn.f32x2 %0, %1, %2, %0;" : "+l"(d) : "l"(a), "l"(b));
}

// ===================== generic SIMT GEMM (small heads + summary) =====================
// C[M,N] = A[M,K] @ B[N,K]^T + bias, + act. ACT: 0 none, 1 sigmoid, 2 tanh.
// H16: also emit fp16 of C into row-major [M][N] half array.
template <int ACT, bool H16>
__global__ __launch_bounds__(256)
void gemm_bias_act(const float* __restrict__ A, const float* __restrict__ B,
                   const float* __restrict__ bias, float* __restrict__ C,
                   int M, int N, int K, __half* __restrict__ gh)
{
    __shared__ float As[16][68];
    __shared__ float Bs[16][68];

    const int tid = threadIdx.x;
    const int m0 = blockIdx.y * 64;
    const int n0 = blockIdx.x * 64;
    const int ty = tid >> 4;
    const int tx = tid & 15;
    const int lr = tid >> 2;
    const int lc = (tid & 3) << 2;

    unsigned long long acc[4][2];
    #pragma unroll
    for (int i = 0; i < 4; i++) { acc[i][0] = 0ull; acc[i][1] = 0ull; }

    for (int k0 = 0; k0 < K; k0 += 16) {
        float4 av = *(const float4*)(A + (size_t)(m0 + lr) * K + k0 + lc);
        float4 bv = make_float4(0.f, 0.f, 0.f, 0.f);
        int bn = n0 + lr;
        if (bn < N) bv = *(const float4*)(B + (size_t)bn * K + k0 + lc);

        As[lc + 0][lr] = av.x; As[lc + 1][lr] = av.y;
        As[lc + 2][lr] = av.z; As[lc + 3][lr] = av.w;
        Bs[lc + 0][lr] = bv.x; Bs[lc + 1][lr] = bv.y;
        Bs[lc + 2][lr] = bv.z; Bs[lc + 3][lr] = bv.w;
        __syncthreads();

        #pragma unroll
        for (int kk = 0; kk < 16; kk++) {
            float4 a4  = *(const float4*)&As[kk][ty << 2];
            float2 b01 = *(const float2*)&Bs[kk][tx << 2];
            float2 b23 = *(const float2*)&Bs[kk][(tx << 2) + 2];
            unsigned long long B01 = pack2(b01.x, b01.y);
            unsigned long long B23 = pack2(b23.x, b23.y);
            unsigned long long a0 = pack2(a4.x, a4.x);
            unsigned long long a1 = pack2(a4.y, a4.y);
            unsigned long long a2 = pack2(a4.z, a4.z);
            unsigned long long a3 = pack2(a4.w, a4.w);
            ffma2(acc[0][0], a0, B01); ffma2(acc[0][1], a0, B23);
            ffma2(acc[1][0], a1, B01); ffma2(acc[1][1], a1, B23);
            ffma2(acc[2][0], a2, B01); ffma2(acc[2][1], a2, B23);
            ffma2(acc[3][0], a3, B01); ffma2(acc[3][1], a3, B23);
        }
        __syncthreads();
    }

    #pragma unroll
    for (int i = 0; i < 4; i++) {
        int m = m0 + (ty << 2) + i;
        float cs[4];
        unpack2(acc[i][0], cs[0], cs[1]);
        unpack2(acc[i][1], cs[2], cs[3]);
        #pragma unroll
        for (int j = 0; j < 4; j++) {
            int n = n0 + (tx << 2) + j;
            if (n < N) {
                float c = cs[j] + bias[n];
                if (ACT == 1) c = 1.f / (1.f + __expf(-c));
                else if (ACT == 2) c = tanhf(c);
                cs[j] = c;
                C[(size_t)m * N + n] = c;
            }
        }
        if (H16) {
            int nb = n0 + (tx << 2);
            __half2* ph = (__half2*)(gh + (size_t)m * 256 + nb);
            ph[0] = __halves2half2(__float2half_rn(cs[0]), __float2half_rn(cs[1]));
            ph[1] = __halves2half2(__float2half_rn(cs[2]), __float2half_rn(cs[3]));
        }
    }
}

// ===================== merged projections (grid.z selects head) =====================
__global__ __launch_bounds__(256)
void proj_gemm(const float* __restrict__ A,
               const float* __restrict__ W0, const float* __restrict__ W1,
               const float* __restrict__ W2, const float* __restrict__ W3,
               const float* __restrict__ b0, const float* __restrict__ b1,
               const float* __restrict__ b2, const float* __restrict__ b3,
               float* __restrict__ C0, float* __restrict__ C1,
               float* __restrict__ C2, float* __restrict__ C3)
{
    const int z = blockIdx.z;
    const float* B; const float* bias; float* C; int act;
    switch (z) {
        case 0:  B = W0; bias = b0; C = C0; act = 0; break;
        case 1:  B = W1; bias = b1; C = C1; act = 0; break;
        case 2:  B = W2; bias = b2; C = C2; act = 1; break;
        default: B = W3; bias = b3; C = C3; act = 1; break;
    }
    const int K = D_INF, N = D_MEM;

    __shared__ float As[16][68];
    __shared__ float Bs[16][68];

    const int tid = threadIdx.x;
    const int m0 = blockIdx.y * 64;
    const int n0 = blockIdx.x * 64;
    const int ty = tid >> 4;
    const int tx = tid & 15;
    const int lr = tid >> 2;
    const int lc = (tid & 3) << 2;

    unsigned long long acc[4][2];
    #pragma unroll
    for (int i = 0; i < 4; i++) { acc[i][0] = 0ull; acc[i][1] = 0ull; }

    for (int k0 = 0; k0 < K; k0 += 16) {
        float4 av = *(const float4*)(A + (size_t)(m0 + lr) * K + k0 + lc);
        float4 bv = *(const float4*)(B + (size_t)(n0 + lr) * K + k0 + lc);
        As[lc + 0][lr] = av.x; As[lc + 1][lr] = av.y;
        As[lc + 2][lr] = av.z; As[lc + 3][lr] = av.w;
        Bs[lc + 0][lr] = bv.x; Bs[lc + 1][lr] = bv.y;
        Bs[lc + 2][lr] = bv.z; Bs[lc + 3][lr] = bv.w;
        __syncthreads();
        #pragma unroll
        for (int kk = 0; kk < 16; kk++) {
            float4 a4  = *(const float4*)&As[kk][ty << 2];
            float2 b01 = *(const float2*)&Bs[kk][tx << 2];
            float2 b23 = *(const float2*)&Bs[kk][(tx << 2) + 2];
            unsigned long long B01 = pack2(b01.x, b01.y);
            unsigned long long B23 = pack2(b23.x, b23.y);
            unsigned long long a0 = pack2(a4.x, a4.x);
            unsigned long long a1 = pack2(a4.y, a4.y);
            unsigned long long a2 = pack2(a4.z, a4.z);
            unsigned long long a3 = pack2(a4.w, a4.w);
            ffma2(acc[0][0], a0, B01); ffma2(acc[0][1], a0, B23);
            ffma2(acc[1][0], a1, B01); ffma2(acc[1][1], a1, B23);
            ffma2(acc[2][0], a2, B01); ffma2(acc[2][1], a2, B23);
            ffma2(acc[3][0], a3, B01); ffma2(acc[3][1], a3, B23);
        }
        __syncthreads();
    }

    #pragma unroll
    for (int i = 0; i < 4; i++) {
        int m = m0 + (ty << 2) + i;
        float cs[4];
        unpack2(acc[i][0], cs[0], cs[1]);
        unpack2(acc[i][1], cs[2], cs[3]);
        #pragma unroll
        for (int j = 0; j < 4; j++) {
            int n = n0 + (tx << 2) + j;
            float c = cs[j] + bias[n];
            if (act == 1) c = 1.f / (1.f + __expf(-c));
            C[(size_t)m * N + n] = c;
        }
    }
}

// ===================== weight fp16 pre-convert (row-major) ==============
__global__ __launch_bounds__(256)
void convert_w16(const float* __restrict__ W, __half* __restrict__ o)
{
    int i = blockIdx.x * 256 + threadIdx.x;     // [0, 32000*64)
    int n  = i >> 6;
    int kq = (i & 63) << 2;
    float4 w = *(const float4*)(W + (size_t)n * 256 + kq);
    size_t off = (size_t)n * 256 + kq;
    ((__half2*)(o + off))[0] = __halves2half2(__float2half_rn(w.x), __float2half_rn(w.y));
    ((__half2*)(o + off))[1] = __halves2half2(__float2half_rn(w.z), __float2half_rn(w.w));
}

// ===================== mma.sync vocab GEMM (fp16, 1-term) =====================
// C[2048,32000] = A[2048,256] @ B[32000,256]^T + bias   (A, B both fp16)
// CTA 128x128, BK=32, 8 warps (2x4), warp tile 64x32, 4-stage cp.async pipeline.
// blockIdx.z selects between the two heads (logit_bias / winner).
#define VK_PAD    40                       // fp16 row stride in SMEM (halfs)
#define VK_TILE   (128 * VK_PAD * 2)       // 10240 bytes per tile
#define VK_STAGE  (2 * VK_TILE)            // A, B = 20480 bytes
#define VK_NSTAGE 4
#define VK_SMEM   (VK_NSTAGE * VK_STAGE)   // 81920

__global__ __launch_bounds__(256, 2)
void vocab_mma(const __half* __restrict__ gA,
               const __half* __restrict__ gB1, const __half* __restrict__ gB2,
               const float* __restrict__ bias1, const float* __restrict__ bias2,
               float* __restrict__ C1, float* __restrict__ C2)
{
    extern __shared__ __align__(16) char smem_raw[];
    const __half* gB = blockIdx.z ? gB2 : gB1;
    const float* bias = blockIdx.z ? bias2 : bias1;
    float* C = blockIdx.z ? C2 : C1;

    const int tid  = threadIdx.x;
    const int warp = tid >> 5, lane = tid & 31;
    const int wm = warp >> 2, wn = warp & 3;        // 2 x 4 warp grid
    const int m0 = blockIdx.y * 128, n0 = blockIdx.x * 128;

    const uint32_t sbase = smem_u32(smem_raw);

    // loader mapping: per tile, thread handles row=tid/2, 32B half tid&1
    const int lrow = tid >> 1;
    const int lhal = tid & 1;

    float acc[4][4][4];
    #pragma unroll
    for (int i = 0; i < 4; i++)
        #pragma unroll
        for (int j = 0; j < 4; j++) {
            acc[i][j][0] = 0.f; acc[i][j][1] = 0.f;
            acc[i][j][2] = 0.f; acc[i][j][3] = 0.f;
        }

    auto issue_stage = [&](int kc) {
        const uint32_t st = sbase + (kc % VK_NSTAGE) * VK_STAGE;
        const size_t gAo = (size_t)(m0 + lrow) * 256 + kc * 32 + lhal * 16;
        const size_t gBo = (size_t)(n0 + lrow) * 256 + kc * 32 + lhal * 16;
        const uint32_t sd = st + lrow * (VK_PAD * 2) + lhal * 32;
        cp_async16(sd + 0 * VK_TILE,      gA + gAo);
        cp_async16(sd + 0 * VK_TILE + 16, gA + gAo + 8);
        cp_async16(sd + 1 * VK_TILE,      gB + gBo);
        cp_async16(sd + 1 * VK_TILE + 16, gB + gBo + 8);
    };

    issue_stage(0); CP_COMMIT();
    issue_stage(1); CP_COMMIT();
    issue_stage(2); CP_COMMIT();

    // per-lane ldmatrix address components
    const uint32_t ar = wm * 64 + (lane & 15);          // + fm*16
    const uint32_t ac16 = (lane >> 4) * 8;              // + h*16
    const int g = lane >> 3, r8 = lane & 7;
    const uint32_t br = wn * 32 + ((g >> 1) * 8) + r8;  // + p*16
    const uint32_t bc = (g & 1) * 8;                    // + h*16

    #pragma unroll
    for (int kc = 0; kc < 8; kc++) {
        if (kc < 5)      { issue_stage(kc + 3); CP_COMMIT(); CP_WAIT(3); }
        else if (kc == 5){ CP_WAIT(2); }
        else if (kc == 6){ CP_WAIT(1); }
        else             { CP_WAIT(0); }
        __syncthreads();

        const uint32_t st = sbase + (kc % VK_NSTAGE) * VK_STAGE;
        const uint32_t tA = st;
        const uint32_t tB = st + VK_TILE;

        #pragma unroll
        for (int h = 0; h < 2; h++) {
            uint32_t a[4][4], b[2][4];
            #pragma unroll
            for (int fm = 0; fm < 4; fm++)
                ldsm4(a[fm], tA + ((ar + fm * 16) * VK_PAD + ac16 + h * 16) * 2);
            #pragma unroll
            for (int p = 0; p < 2; p++)
                ldsm4(b[p], tB + ((br + p * 16) * VK_PAD + bc + h * 16) * 2);

            #pragma unroll
            for (int fm = 0; fm < 4; fm++)
                #pragma unroll
                for (int fn = 0; fn < 4; fn++) {
                    const int p = fn >> 1, q = fn & 1;
                    mma16816h(acc[fm][fn], a[fm], b[p][q * 2], b[p][q * 2 + 1]);
                }
        }
        __syncthreads();
    }

    // epilogue: direct float2 stores with bias
    float2 bv[4];
    #pragma unroll
    for (int fn = 0; fn < 4; fn++)
        bv[fn] = *(const float2*)(bias + n0 + wn * 32 + fn * 8 + (lane & 3) * 2);

    #pragma unroll
    for (int fm = 0; fm < 4; fm++) {
        const int r0 = m0 + wm * 64 + fm * 16 + (lane >> 2);
        #pragma unroll
        for (int fn = 0; fn < 4; fn++) {
            const int col = n0 + wn * 32 + fn * 8 + (lane & 3) * 2;
            float2 v0 = make_float2(acc[fm][fn][0] + bv[fn].x, acc[fm][fn][1] + bv[fn].y);
            float2 v1 = make_float2(acc[fm][fn][2] + bv[fn].x, acc[fm][fn][3] + bv[fn].y);
            *(float2*)(C + (size_t)r0 * VOCAB + col)       = v0;
            *(float2*)(C + (size_t)(r0 + 8) * VOCAB + col) = v1;
        }
    }
}

// ===================== row L2-normalize =====================
__global__ __launch_bounds__(256)
void normalize_rows(float* __restrict__ X)
{
    int w = (blockIdx.x * blockDim.x + threadIdx.x) >> 5;
    int lane = threadIdx.x & 31;
    if (w >= M_ROWS) return;
    float* row = X + (size_t)w * D_MEM;
    float x[8];
    float ss = 0.f;
    #pragma unroll
    for (int j = 0; j < 8; j++) { x[j] = row[lane + 32 * j]; ss += x[j] * x[j]; }
    #pragma unroll
    for (int o = 16; o; o >>= 1) ss += __shfl_xor_sync(0xffffffffu, ss, o);
    float inv = 1.f / fmaxf(sqrtf(ss), 1e-12f);
    #pragma unroll
    for (int j = 0; j < 8; j++) row[lane + 32 * j] = x[j] * inv;
}

__device__ __forceinline__ float warp_sum(float x) {
    #pragma unroll
    for (int o = 16; o; o >>= 1) x += __shfl_xor_sync(0xffffffffu, x, o);
    return x;
}

// ===================== gated delta-rule scan =====================
// ||k||=1  =>  summary_raw = lam*read + corr  (no second reduction needed)
__global__ __launch_bounds__(128)
void scan_kernel(const float* __restrict__ Kn, const float* __restrict__ V,
                 const float* __restrict__ Beta, const float* __restrict__ Lam,
                 const float* __restrict__ Mem0, float* __restrict__ Sraw,
                 float* __restrict__ MemOut)
{
    const int wid  = threadIdx.x >> 5;
    const int lane = threadIdx.x & 31;
    const int wg = blockIdx.x * 4 + wid;
    const int b = wg >> 8;
    const int r = wg & 255;

    const float* kb = Kn  + (size_t)b * T_SEQ * D_MEM;
    const float* vb = V   + (size_t)b * T_SEQ * D_MEM + r;
    const float* bb = Beta+ (size_t)b * T_SEQ * D_MEM + r;
    const float* lb = Lam + (size_t)b * T_SEQ * D_MEM + r;

    float m[8];
    #pragma unroll
    for (int j = 0; j < 8; j++)
        m[j] = Mem0[(size_t)b * D_MEM * D_MEM + (size_t)r * D_MEM + lane + 32 * j];

    float kk[8], vt, bt, lt;
    #pragma unroll
    for (int j = 0; j < 8; j++) kk[j] = kb[lane + 32 * j];
    vt = vb[0]; bt = bb[0]; lt = lb[0];

    for (int t = 0; t < T_SEQ; t++) {
        float kn[8], vn = 0.f, bn = 0.f, ln = 0.f;
        if (t + 1 < T_SEQ) {
            const float* kp = kb + (size_t)(t + 1) * D_MEM;
            #pragma unroll
            for (int j = 0; j < 8; j++) kn[j] = kp[lane + 32 * j];
            vn = vb[(size_t)(t + 1) * D_MEM];
            bn = bb[(size_t)(t + 1) * D_MEM];
            ln = lb[(size_t)(t + 1) * D_MEM];
        } else {
            #pragma unroll
            for (int j = 0; j < 8; j++) kn[j] = 0.f;
        }

        float s0 = m[0] * kk[0] + m[2] * kk[2];
        float s1 = m[1] * kk[1] + m[3] * kk[3];
        s0 += m[4] * kk[4] + m[6] * kk[6];
        s1 += m[5] * kk[5] + m[7] * kk[7];
        float rd = warp_sum(s0 + s1);

        float corr = (vt - rd) * bt;
        float s2 = lt * rd + corr;

        if (lane == 0)
            Sraw[(size_t)b * T_SEQ * D_MEM + (size_t)t * D_MEM + r] = s2;

        #pragma unroll
        for (int j = 0; j < 8; j++) {
            m[j] = m[j] * lt + corr * kk[j];
            kk[j] = kn[j];
        }
        vt = vn; bt = bn; lt = ln;
    }

    #pragma unroll
    for (int j = 0; j < 8; j++)
        MemOut[(size_t)b * D_MEM * D_MEM + (size_t)r * D_MEM + lane + 32 * j] = m[j];
}

// ===================== launch =====================
extern "C" void kernel_launch(void* const* d_in, const int* in_sizes, int n_in,
                              void* d_out, int out_size)
{
    const float* cf    = (const float*)d_in[0];
    const float* mem0  = (const float*)d_in[1];
    const float* Wk    = (const float*)d_in[2];
    const float* bk    = (const float*)d_in[3];
    const float* Wv    = (const float*)d_in[4];
    const float* bv    = (const float*)d_in[5];
    const float* Wbeta = (const float*)d_in[6];
    const float* bbeta = (const float*)d_in[7];
    const float* Wlam  = (const float*)d_in[8];
    const float* blam  = (const float*)d_in[9];
    const float* Wsum  = (const float*)d_in[10];
    const float* bsum  = (const float*)d_in[11];
    const float* Wlb   = (const float*)d_in[12];
    const float* blb   = (const float*)d_in[13];
    const float* Wph   = (const float*)d_in[14];
    const float* bph   = (const float*)d_in[15];
    const float* Wwin  = (const float*)d_in[16];
    const float* bwin  = (const float*)d_in[17];
    const float* Wmar  = (const float*)d_in[18];
    const float* bmar  = (const float*)d_in[19];

    float* out = (float*)d_out;
    float* out_mem = out + OFF_MEM;
    float* out_sum = out + OFF_SUM;
    float* out_lb  = out + OFF_LB;
    float* out_ph  = out + OFF_PH;
    float* out_win = out + OFF_WIN;
    float* out_mar = out + OFF_MAR;

    float *pk, *pv, *pb, *pl, *ps;
    __half *pA16, *pW1, *pW2;
    cudaGetSymbolAddress((void**)&pk, g_k);
    cudaGetSymbolAddress((void**)&pv, g_v);
    cudaGetSymbolAddress((void**)&pb, g_beta);
    cudaGetSymbolAddress((void**)&pl, g_lam);
    cudaGetSymbolAddress((void**)&ps, g_sraw);
    cudaGetSymbolAddress((void**)&pA16, g_A16);
    cudaGetSymbolAddress((void**)&pW1, g_W1f);
    cudaGetSymbolAddress((void**)&pW2, g_W2f);

    cudaFuncSetAttribute(vocab_mma, cudaFuncAttributeMaxDynamicSharedMemorySize, VK_SMEM);

    // weight pre-convert (independent of the recurrence path)
    convert_w16<<<8000, 256>>>(Wlb,  pW1);
    convert_w16<<<8000, 256>>>(Wwin, pW2);

    // projections (merged)
    proj_gemm<<<dim3(4, 32, 4), 256>>>(cf, Wk, Wv, Wbeta, Wlam,
                                       bk, bv, bbeta, blam,
                                       pk, pv, pb, pl);

    normalize_rows<<<256, 256>>>(pk);

    scan_kernel<<<128, 128>>>(pk, pv, pb, pl, mem0, ps, out_mem);

    // summary GEMM (tanh) + fp16 side output
    gemm_bias_act<2, true><<<dim3(4, 32), 256>>>(ps, Wsum, bsum, out_sum,
                                                 M_ROWS, D_MEM, D_MEM, pA16);

    // both vocab GEMMs in one launch (grid.z selects head)
    vocab_mma<<<dim3(250, 16, 2), 256, VK_SMEM>>>(pA16, pW1, pW2, blb, bwin,
                                                  out_lb, out_win);

    // small heads
    gemm_bias_act<0, false><<<dim3(1, 32), 256>>>(out_sum, Wph,  bph,  out_ph,
                                                  M_ROWS, PHASE_N, D_MEM, nullptr);
    gemm_bias_act<0, false><<<dim3(1, 32), 256>>>(out_sum, Wmar, bmar, out_mar,
                                                  M_ROWS, MARGIN_N, D_MEM, nullptr);
}

// round 12
// speedup vs baseline: 3.4220x; 1.2519x over previous
#include <cuda_runtime.h>
#include <cuda_fp16.h>
#include <math.h>
#include <stdint.h>

// Problem constants
#define B_SZ    2
#define T_SEQ   1024
#define D_INF   1024
#define D_MEM   256
#define VOCAB   32000
#define PHASE_N 8
#define MARGIN_N 4
#define M_ROWS  (B_SZ * T_SEQ)   // 2048

// Output layout offsets (float elements)
#define OFF_MEM   0
#define OFF_SUM   131072
#define OFF_LB    655360
#define OFF_PH    66191360
#define OFF_WIN   66207744
#define OFF_MAR   131743744

// Scratch device globals
__device__ float g_k   [M_ROWS * D_MEM];
__device__ float g_v   [M_ROWS * D_MEM];
__device__ float g_beta[M_ROWS * D_MEM];
__device__ float g_lam [M_ROWS * D_MEM];
__device__ float g_sraw[M_ROWS * D_MEM];
// fp16 operands for the vocab GEMMs
__device__ __half g_A16 [M_ROWS * D_MEM];          // fp16(summary)
__device__ __half g_W1f [(size_t)VOCAB * D_MEM];   // fp16(Wlb)
__device__ __half g_W2f [(size_t)VOCAB * D_MEM];   // fp16(Wwin)

// ===================== helpers =====================
__device__ __forceinline__ uint32_t smem_u32(const void* p) {
    uint32_t a;
    asm("{ .reg .u64 t; cvta.to.shared.u64 t, %1; cvt.u32.u64 %0, t; }" : "=r"(a) : "l"(p));
    return a;
}
__device__ __forceinline__ void cp_async16(uint32_t dst, const void* src) {
    asm volatile("cp.async.cg.shared.global [%0], [%1], 16;" :: "r"(dst), "l"(src));
}
#define CP_COMMIT() asm volatile("cp.async.commit_group;" ::: "memory")
#define CP_WAIT(N)  asm volatile("cp.async.wait_group %0;" :: "n"(N) : "memory")

__device__ __forceinline__ void ldsm4(uint32_t* r, uint32_t addr) {
    asm volatile("ldmatrix.sync.aligned.m8n8.x4.shared.b16 {%0,%1,%2,%3}, [%4];"
        : "=r"(r[0]), "=r"(r[1]), "=r"(r[2]), "=r"(r[3]) : "r"(addr));
}
__device__ __forceinline__ void mma16816h(float* c, const uint32_t* a,
                                          uint32_t b0, uint32_t b1) {
    asm volatile(
        "mma.sync.aligned.m16n8k16.row.col.f32.f16.f16.f32 "
        "{%0,%1,%2,%3}, {%4,%5,%6,%7}, {%8,%9}, {%0,%1,%2,%3};"
        : "+f"(c[0]), "+f"(c[1]), "+f"(c[2]), "+f"(c[3])
        : "r"(a[0]), "r"(a[1]), "r"(a[2]), "r"(a[3]), "r"(b0), "r"(b1));
}

// packed f32x2 (FFMA2)
__device__ __forceinline__ unsigned long long pack2(float x, float y) {
    unsigned long long r;
    asm("mov.b64 %0, {%1, %2};" : "=l"(r) : "f"(x), "f"(y));
    return r;
}
__device__ __forceinline__ void unpack2(unsigned long long p, float& x, float& y) {
    asm("mov.b64 {%0, %1}, %2;" : "=f"(x), "=f"(y) : "l"(p));
}
__device__ __forceinline__ void ffma2(unsigned long long& d, unsigned long long a,
                                      unsigned long long b) {
    asm("fma.rn.f32x2 %0, %1, %2, %0;" : "+l"(d) : "l"(a), "l"(b));
}

// ===================== generic SIMT GEMM (small heads + summary) =====================
// C[M,N] = A[M,K] @ B[N,K]^T + bias, + act. ACT: 0 none, 1 sigmoid, 2 tanh.
// H16: also emit fp16 of C into row-major [M][N] half array.
template <int ACT, bool H16>
__global__ __launch_bounds__(256)
void gemm_bias_act(const float* __restrict__ A, const float* __restrict__ B,
                   const float* __restrict__ bias, float* __restrict__ C,
                   int M, int N, int K, __half* __restrict__ gh)
{
    __shared__ float As[16][68];
    __shared__ float Bs[16][68];

    const int tid = threadIdx.x;
    const int m0 = blockIdx.y * 64;
    const int n0 = blockIdx.x * 64;
    const int ty = tid >> 4;
    const int tx = tid & 15;
    const int lr = tid >> 2;
    const int lc = (tid & 3) << 2;

    unsigned long long acc[4][2];
    #pragma unroll
    for (int i = 0; i < 4; i++) { acc[i][0] = 0ull; acc[i][1] = 0ull; }

    for (int k0 = 0; k0 < K; k0 += 16) {
        float4 av = *(const float4*)(A + (size_t)(m0 + lr) * K + k0 + lc);
        float4 bv = make_float4(0.f, 0.f, 0.f, 0.f);
        int bn = n0 + lr;
        if (bn < N) bv = *(const float4*)(B + (size_t)bn * K + k0 + lc);

        As[lc + 0][lr] = av.x; As[lc + 1][lr] = av.y;
        As[lc + 2][lr] = av.z; As[lc + 3][lr] = av.w;
        Bs[lc + 0][lr] = bv.x; Bs[lc + 1][lr] = bv.y;
        Bs[lc + 2][lr] = bv.z; Bs[lc + 3][lr] = bv.w;
        __syncthreads();

        #pragma unroll
        for (int kk = 0; kk < 16; kk++) {
            float4 a4  = *(const float4*)&As[kk][ty << 2];
            float2 b01 = *(const float2*)&Bs[kk][tx << 2];
            float2 b23 = *(const float2*)&Bs[kk][(tx << 2) + 2];
            unsigned long long B01 = pack2(b01.x, b01.y);
            unsigned long long B23 = pack2(b23.x, b23.y);
            unsigned long long a0 = pack2(a4.x, a4.x);
            unsigned long long a1 = pack2(a4.y, a4.y);
            unsigned long long a2 = pack2(a4.z, a4.z);
            unsigned long long a3 = pack2(a4.w, a4.w);
            ffma2(acc[0][0], a0, B01); ffma2(acc[0][1], a0, B23);
            ffma2(acc[1][0], a1, B01); ffma2(acc[1][1], a1, B23);
            ffma2(acc[2][0], a2, B01); ffma2(acc[2][1], a2, B23);
            ffma2(acc[3][0], a3, B01); ffma2(acc[3][1], a3, B23);
        }
        __syncthreads();
    }

    #pragma unroll
    for (int i = 0; i < 4; i++) {
        int m = m0 + (ty << 2) + i;
        float cs[4];
        unpack2(acc[i][0], cs[0], cs[1]);
        unpack2(acc[i][1], cs[2], cs[3]);
        #pragma unroll
        for (int j = 0; j < 4; j++) {
            int n = n0 + (tx << 2) + j;
            if (n < N) {
                float c = cs[j] + bias[n];
                if (ACT == 1) c = 1.f / (1.f + __expf(-c));
                else if (ACT == 2) c = tanhf(c);
                cs[j] = c;
                C[(size_t)m * N + n] = c;
            }
        }
        if (H16) {
            int nb = n0 + (tx << 2);
            __half2* ph = (__half2*)(gh + (size_t)m * 256 + nb);
            ph[0] = __halves2half2(__float2half_rn(cs[0]), __float2half_rn(cs[1]));
            ph[1] = __halves2half2(__float2half_rn(cs[2]), __float2half_rn(cs[3]));
        }
    }
}

// ===================== merged projections (grid.z selects head) =====================
__global__ __launch_bounds__(256)
void proj_gemm(const float* __restrict__ A,
               const float* __restrict__ W0, const float* __restrict__ W1,
               const float* __restrict__ W2, const float* __restrict__ W3,
               const float* __restrict__ b0, const float* __restrict__ b1,
               const float* __restrict__ b2, const float* __restrict__ b3,
               float* __restrict__ C0, float* __restrict__ C1,
               float* __restrict__ C2, float* __restrict__ C3)
{
    const int z = blockIdx.z;
    const float* B; const float* bias; float* C; int act;
    switch (z) {
        case 0:  B = W0; bias = b0; C = C0; act = 0; break;
        case 1:  B = W1; bias = b1; C = C1; act = 0; break;
        case 2:  B = W2; bias = b2; C = C2; act = 1; break;
        default: B = W3; bias = b3; C = C3; act = 1; break;
    }
    const int K = D_INF, N = D_MEM;

    __shared__ float As[16][68];
    __shared__ float Bs[16][68];

    const int tid = threadIdx.x;
    const int m0 = blockIdx.y * 64;
    const int n0 = blockIdx.x * 64;
    const int ty = tid >> 4;
    const int tx = tid & 15;
    const int lr = tid >> 2;
    const int lc = (tid & 3) << 2;

    unsigned long long acc[4][2];
    #pragma unroll
    for (int i = 0; i < 4; i++) { acc[i][0] = 0ull; acc[i][1] = 0ull; }

    for (int k0 = 0; k0 < K; k0 += 16) {
        float4 av = *(const float4*)(A + (size_t)(m0 + lr) * K + k0 + lc);
        float4 bv = *(const float4*)(B + (size_t)(n0 + lr) * K + k0 + lc);
        As[lc + 0][lr] = av.x; As[lc + 1][lr] = av.y;
        As[lc + 2][lr] = av.z; As[lc + 3][lr] = av.w;
        Bs[lc + 0][lr] = bv.x; Bs[lc + 1][lr] = bv.y;
        Bs[lc + 2][lr] = bv.z; Bs[lc + 3][lr] = bv.w;
        __syncthreads();
        #pragma unroll
        for (int kk = 0; kk < 16; kk++) {
            float4 a4  = *(const float4*)&As[kk][ty << 2];
            float2 b01 = *(const float2*)&Bs[kk][tx << 2];
            float2 b23 = *(const float2*)&Bs[kk][(tx << 2) + 2];
            unsigned long long B01 = pack2(b01.x, b01.y);
            unsigned long long B23 = pack2(b23.x, b23.y);
            unsigned long long a0 = pack2(a4.x, a4.x);
            unsigned long long a1 = pack2(a4.y, a4.y);
            unsigned long long a2 = pack2(a4.z, a4.z);
            unsigned long long a3 = pack2(a4.w, a4.w);
            ffma2(acc[0][0], a0, B01); ffma2(acc[0][1], a0, B23);
            ffma2(acc[1][0], a1, B01); ffma2(acc[1][1], a1, B23);
            ffma2(acc[2][0], a2, B01); ffma2(acc[2][1], a2, B23);
            ffma2(acc[3][0], a3, B01); ffma2(acc[3][1], a3, B23);
        }
        __syncthreads();
    }

    #pragma unroll
    for (int i = 0; i < 4; i++) {
        int m = m0 + (ty << 2) + i;
        float cs[4];
        unpack2(acc[i][0], cs[0], cs[1]);
        unpack2(acc[i][1], cs[2], cs[3]);
        #pragma unroll
        for (int j = 0; j < 4; j++) {
            int n = n0 + (tx << 2) + j;
            float c = cs[j] + bias[n];
            if (act == 1) c = 1.f / (1.f + __expf(-c));
            C[(size_t)m * N + n] = c;
        }
    }
}

// ===================== weight fp16 pre-convert (merged, grid.z selects W) ======
__global__ __launch_bounds__(256)
void convert_w16(const float* __restrict__ W1, const float* __restrict__ W2,
                 __half* __restrict__ o1, __half* __restrict__ o2)
{
    const float* W = blockIdx.z ? W2 : W1;
    __half* o = blockIdx.z ? o2 : o1;
    int i = blockIdx.x * 256 + threadIdx.x;     // [0, 32000*64)
    int n  = i >> 6;
    int kq = (i & 63) << 2;
    float4 w = *(const float4*)(W + (size_t)n * 256 + kq);
    size_t off = (size_t)n * 256 + kq;
    ((__half2*)(o + off))[0] = __halves2half2(__float2half_rn(w.x), __float2half_rn(w.y));
    ((__half2*)(o + off))[1] = __halves2half2(__float2half_rn(w.z), __float2half_rn(w.w));
}

// ===================== mma.sync vocab GEMM (fp16, 1-term) =====================
// C[2048,32000] = A[2048,256] @ B[32000,256]^T + bias   (A, B both fp16)
// CTA 128x128, BK=32, 8 warps (2x4), warp tile 64x32, 4-stage cp.async pipeline.
// blockIdx.z selects between the two heads (logit_bias / winner).
#define VK_PAD    40                       // fp16 row stride in SMEM (halfs)
#define VK_TILE   (128 * VK_PAD * 2)       // 10240 bytes per tile
#define VK_STAGE  (2 * VK_TILE)            // A, B = 20480 bytes
#define VK_NSTAGE 4
#define VK_SMEM   (VK_NSTAGE * VK_STAGE)   // 81920

__global__ __launch_bounds__(256, 2)
void vocab_mma(const __half* __restrict__ gA,
               const __half* __restrict__ gB1, const __half* __restrict__ gB2,
               const float* __restrict__ bias1, const float* __restrict__ bias2,
               float* __restrict__ C1, float* __restrict__ C2)
{
    extern __shared__ __align__(16) char smem_raw[];
    const __half* gB = blockIdx.z ? gB2 : gB1;
    const float* bias = blockIdx.z ? bias2 : bias1;
    float* C = blockIdx.z ? C2 : C1;

    const int tid  = threadIdx.x;
    const int warp = tid >> 5, lane = tid & 31;
    const int wm = warp >> 2, wn = warp & 3;        // 2 x 4 warp grid
    const int m0 = blockIdx.y * 128, n0 = blockIdx.x * 128;

    const uint32_t sbase = smem_u32(smem_raw);

    // loader mapping: per tile, thread handles row=tid/2, 32B half tid&1
    const int lrow = tid >> 1;
    const int lhal = tid & 1;

    float acc[4][4][4];
    #pragma unroll
    for (int i = 0; i < 4; i++)
        #pragma unroll
        for (int j = 0; j < 4; j++) {
            acc[i][j][0] = 0.f; acc[i][j][1] = 0.f;
            acc[i][j][2] = 0.f; acc[i][j][3] = 0.f;
        }

    auto issue_stage = [&](int kc) {
        const uint32_t st = sbase + (kc % VK_NSTAGE) * VK_STAGE;
        const size_t gAo = (size_t)(m0 + lrow) * 256 + kc * 32 + lhal * 16;
        const size_t gBo = (size_t)(n0 + lrow) * 256 + kc * 32 + lhal * 16;
        const uint32_t sd = st + lrow * (VK_PAD * 2) + lhal * 32;
        cp_async16(sd + 0 * VK_TILE,      gA + gAo);
        cp_async16(sd + 0 * VK_TILE + 16, gA + gAo + 8);
        cp_async16(sd + 1 * VK_TILE,      gB + gBo);
        cp_async16(sd + 1 * VK_TILE + 16, gB + gBo + 8);
    };

    issue_stage(0); CP_COMMIT();
    issue_stage(1); CP_COMMIT();
    issue_stage(2); CP_COMMIT();

    // per-lane ldmatrix address components
    const uint32_t ar = wm * 64 + (lane & 15);          // + fm*16
    const uint32_t ac16 = (lane >> 4) * 8;              // + h*16
    const int g = lane >> 3, r8 = lane & 7;
    const uint32_t br = wn * 32 + ((g >> 1) * 8) + r8;  // + p*16
    const uint32_t bc = (g & 1) * 8;                    // + h*16

    #pragma unroll
    for (int kc = 0; kc < 8; kc++) {
        if (kc < 5)      { issue_stage(kc + 3); CP_COMMIT(); CP_WAIT(3); }
        else if (kc == 5){ CP_WAIT(2); }
        else if (kc == 6){ CP_WAIT(1); }
        else             { CP_WAIT(0); }
        __syncthreads();

        const uint32_t st = sbase + (kc % VK_NSTAGE) * VK_STAGE;
        const uint32_t tA = st;
        const uint32_t tB = st + VK_TILE;

        #pragma unroll
        for (int h = 0; h < 2; h++) {
            uint32_t a[4][4], b[2][4];
            #pragma unroll
            for (int fm = 0; fm < 4; fm++)
                ldsm4(a[fm], tA + ((ar + fm * 16) * VK_PAD + ac16 + h * 16) * 2);
            #pragma unroll
            for (int p = 0; p < 2; p++)
                ldsm4(b[p], tB + ((br + p * 16) * VK_PAD + bc + h * 16) * 2);

            #pragma unroll
            for (int fm = 0; fm < 4; fm++)
                #pragma unroll
                for (int fn = 0; fn < 4; fn++) {
                    const int p = fn >> 1, q = fn & 1;
                    mma16816h(acc[fm][fn], a[fm], b[p][q * 2], b[p][q * 2 + 1]);
                }
        }
        __syncthreads();
    }

    // epilogue: direct float2 stores with bias
    float2 bv[4];
    #pragma unroll
    for (int fn = 0; fn < 4; fn++)
        bv[fn] = *(const float2*)(bias + n0 + wn * 32 + fn * 8 + (lane & 3) * 2);

    #pragma unroll
    for (int fm = 0; fm < 4; fm++) {
        const int r0 = m0 + wm * 64 + fm * 16 + (lane >> 2);
        #pragma unroll
        for (int fn = 0; fn < 4; fn++) {
            const int col = n0 + wn * 32 + fn * 8 + (lane & 3) * 2;
            float2 v0 = make_float2(acc[fm][fn][0] + bv[fn].x, acc[fm][fn][1] + bv[fn].y);
            float2 v1 = make_float2(acc[fm][fn][2] + bv[fn].x, acc[fm][fn][3] + bv[fn].y);
            *(float2*)(C + (size_t)r0 * VOCAB + col)       = v0;
            *(float2*)(C + (size_t)(r0 + 8) * VOCAB + col) = v1;
        }
    }
}

// ===================== row L2-normalize =====================
__global__ __launch_bounds__(256)
void normalize_rows(float* __restrict__ X)
{
    int w = (blockIdx.x * blockDim.x + threadIdx.x) >> 5;
    int lane = threadIdx.x & 31;
    if (w >= M_ROWS) return;
    float* row = X + (size_t)w * D_MEM;
    float x[8];
    float ss = 0.f;
    #pragma unroll
    for (int j = 0; j < 8; j++) { x[j] = row[lane + 32 * j]; ss += x[j] * x[j]; }
    #pragma unroll
    for (int o = 16; o; o >>= 1) ss += __shfl_xor_sync(0xffffffffu, ss, o);
    float inv = 1.f / fmaxf(sqrtf(ss), 1e-12f);
    #pragma unroll
    for (int j = 0; j < 8; j++) row[lane + 32 * j] = x[j] * inv;
}

// ===================== gated delta-rule scan (pipelined recursion) ============
// read_t = M_t.k_t = lam_{t-1}*(M_{t-1}.k_t) + corr_{t-1}*(k_{t-1}.k_t)
//        = lam_{t-1}*D1_t + corr_{t-1}*D2_t
// D1/D2 reductions for step t+1 start during step t (pre-update state), so the
// 150-cyc shfl butterfly is off the corr critical path: ~2x shorter recurrence.
// ||k||=1 => summary_raw = lam*read + corr. Distance-2 prefetch (3-slot ring,
// unroll 3 -> static registers) covers L2 latency.
__global__ __launch_bounds__(128)
void scan_kernel(const float* __restrict__ Kn, const float* __restrict__ V,
                 const float* __restrict__ Beta, const float* __restrict__ Lam,
                 const float* __restrict__ Mem0, float* __restrict__ Sraw,
                 float* __restrict__ MemOut)
{
    const int wid  = threadIdx.x >> 5;
    const int lane = threadIdx.x & 31;
    const int wg = blockIdx.x * 4 + wid;
    const int b = wg >> 8;
    const int r = wg & 255;

    const float* kb = Kn  + (size_t)b * T_SEQ * D_MEM + lane;
    const float* vb = V   + (size_t)b * T_SEQ * D_MEM + r;
    const float* bb = Beta+ (size_t)b * T_SEQ * D_MEM + r;
    const float* lb = Lam + (size_t)b * T_SEQ * D_MEM + r;
    float* sb = Sraw + (size_t)b * T_SEQ * D_MEM + r;

    float m[8];
    #pragma unroll
    for (int j = 0; j < 8; j++)
        m[j] = Mem0[(size_t)b * D_MEM * D_MEM + (size_t)r * D_MEM + lane + 32 * j];

    // 3-slot rings: slot (t % 3) holds step t's data
    float kr[3][8];
    float vr[3], br[3], lr[3];
    #pragma unroll
    for (int s = 0; s < 3; s++) {
        #pragma unroll
        for (int j = 0; j < 8; j++) kr[s][j] = kb[(size_t)s * D_MEM + 32 * j];
        vr[s] = vb[(size_t)s * D_MEM];
        br[s] = bb[(size_t)s * D_MEM];
        lr[s] = lb[(size_t)s * D_MEM];
    }

    float D1, D2, lp, corrp;

    // ---- boot: t = 0 (direct reduction of read_0, plus D's for t=1) ----
    {
        float p0 = 0.f, p1 = 0.f, q1a = 0.f, q1b = 0.f, q2a = 0.f, q2b = 0.f;
        #pragma unroll
        for (int j = 0; j < 8; j++) {
            if (j & 1) { p1 += m[j] * kr[0][j]; q1b += m[j] * kr[1][j]; q2b += kr[0][j] * kr[1][j]; }
            else       { p0 += m[j] * kr[0][j]; q1a += m[j] * kr[1][j]; q2a += kr[0][j] * kr[1][j]; }
        }
        float p = p0 + p1, q1 = q1a + q1b, q2 = q2a + q2b;
        #pragma unroll
        for (int o = 16; o; o >>= 1) {
            p  += __shfl_xor_sync(0xffffffffu, p,  o);
            q1 += __shfl_xor_sync(0xffffffffu, q1, o);
            q2 += __shfl_xor_sync(0xffffffffu, q2, o);
        }
        const float vt = vr[0], bt = br[0], lt = lr[0];
        float corr = (vt - p) * bt;
        if (lane == 0) sb[0] = lt * p + corr;
        #pragma unroll
        for (int j = 0; j < 8; j++) m[j] = m[j] * lt + corr * kr[0][j];
        D1 = q1; D2 = q2; lp = lt; corrp = corr;
        // prefetch t = 3 into slot 0
        #pragma unroll
        for (int j = 0; j < 8; j++) kr[0][j] = kb[(size_t)3 * D_MEM + 32 * j];
        vr[0] = vb[(size_t)3 * D_MEM];
        br[0] = bb[(size_t)3 * D_MEM];
        lr[0] = lb[(size_t)3 * D_MEM];
    }

    // ---- main loop: t = 1 .. 1023 (1023 = 341 * 3 -> unroll 3 statically) ----
    #pragma unroll 3
    for (int t = 1; t < T_SEQ; t++) {
        const int cur = t % 3, nxt = (t + 1) % 3;

        // partials for next step's reductions (pre-update m = M_t)
        float q1a = 0.f, q1b = 0.f, q2a = 0.f, q2b = 0.f;
        #pragma unroll
        for (int j = 0; j < 8; j++) {
            if (j & 1) { q1b += m[j] * kr[nxt][j]; q2b += kr[cur][j] * kr[nxt][j]; }
            else       { q1a += m[j] * kr[nxt][j]; q2a += kr[cur][j] * kr[nxt][j]; }
        }
        float q1 = q1a + q1b, q2 = q2a + q2b;

        // scalar chain using previous step's reductions
        float read = lp * D1 + corrp * D2;
        const float vt = vr[cur], bt = br[cur], lt = lr[cur];
        float corr = (vt - read) * bt;
        if (lane == 0) sb[(size_t)t * D_MEM] = lt * read + corr;
        #pragma unroll
        for (int j = 0; j < 8; j++) m[j] = m[j] * lt + corr * kr[cur][j];

        // interleaved butterflies (off the corr critical path)
        #pragma unroll
        for (int o = 16; o; o >>= 1) {
            q1 += __shfl_xor_sync(0xffffffffu, q1, o);
            q2 += __shfl_xor_sync(0xffffffffu, q2, o);
        }
        D1 = q1; D2 = q2; lp = lt; corrp = corr;

        // prefetch t+3 (clamped) into the slot just freed
        const int ii = (t + 3 < T_SEQ) ? (t + 3) : (T_SEQ - 1);
        #pragma unroll
        for (int j = 0; j < 8; j++) kr[cur][j] = kb[(size_t)ii * D_MEM + 32 * j];
        vr[cur] = vb[(size_t)ii * D_MEM];
        br[cur] = bb[(size_t)ii * D_MEM];
        lr[cur] = lb[(size_t)ii * D_MEM];
    }

    #pragma unroll
    for (int j = 0; j < 8; j++)
        MemOut[(size_t)b * D_MEM * D_MEM + (size_t)r * D_MEM + lane + 32 * j] = m[j];
}

// ===================== launch =====================
extern "C" void kernel_launch(void* const* d_in, const int* in_sizes, int n_in,
                              void* d_out, int out_size)
{
    const float* cf    = (const float*)d_in[0];
    const float* mem0  = (const float*)d_in[1];
    const float* Wk    = (const float*)d_in[2];
    const float* bk    = (const float*)d_in[3];
    const float* Wv    = (const float*)d_in[4];
    const float* bv    = (const float*)d_in[5];
    const float* Wbeta = (const float*)d_in[6];
    const float* bbeta = (const float*)d_in[7];
    const float* Wlam  = (const float*)d_in[8];
    const float* blam  = (const float*)d_in[9];
    const float* Wsum  = (const float*)d_in[10];
    const float* bsum  = (const float*)d_in[11];
    const float* Wlb   = (const float*)d_in[12];
    const float* blb   = (const float*)d_in[13];
    const float* Wph   = (const float*)d_in[14];
    const float* bph   = (const float*)d_in[15];
    const float* Wwin  = (const float*)d_in[16];
    const float* bwin  = (const float*)d_in[17];
    const float* Wmar  = (const float*)d_in[18];
    const float* bmar  = (const float*)d_in[19];

    float* out = (float*)d_out;
    float* out_mem = out + OFF_MEM;
    float* out_sum = out + OFF_SUM;
    float* out_lb  = out + OFF_LB;
    float* out_ph  = out + OFF_PH;
    float* out_win = out + OFF_WIN;
    float* out_mar = out + OFF_MAR;

    float *pk, *pv, *pb, *pl, *ps;
    __half *pA16, *pW1, *pW2;
    cudaGetSymbolAddress((void**)&pk, g_k);
    cudaGetSymbolAddress((void**)&pv, g_v);
    cudaGetSymbolAddress((void**)&pb, g_beta);
    cudaGetSymbolAddress((void**)&pl, g_lam);
    cudaGetSymbolAddress((void**)&ps, g_sraw);
    cudaGetSymbolAddress((void**)&pA16, g_A16);
    cudaGetSymbolAddress((void**)&pW1, g_W1f);
    cudaGetSymbolAddress((void**)&pW2, g_W2f);

    cudaFuncSetAttribute(vocab_mma, cudaFuncAttributeMaxDynamicSharedMemorySize, VK_SMEM);

    // weight pre-convert (merged; independent of the recurrence path)
    convert_w16<<<dim3(8000, 1, 2), 256>>>(Wlb, Wwin, pW1, pW2);

    // projections (merged)
    proj_gemm<<<dim3(4, 32, 4), 256>>>(cf, Wk, Wv, Wbeta, Wlam,
                                       bk, bv, bbeta, blam,
                                       pk, pv, pb, pl);

    normalize_rows<<<256, 256>>>(pk);

    scan_kernel<<<128, 128>>>(pk, pv, pb, pl, mem0, ps, out_mem);

    // summary GEMM (tanh) + fp16 side output
    gemm_bias_act<2, true><<<dim3(4, 32), 256>>>(ps, Wsum, bsum, out_sum,
                                                 M_ROWS, D_MEM, D_MEM, pA16);

    // both vocab GEMMs in one launch (grid.z selects head)
    vocab_mma<<<dim3(250, 16, 2), 256, VK_SMEM>>>(pA16, pW1, pW2, blb, bwin,
                                                  out_lb, out_win);

    // small heads
    gemm_bias_act<0, false><<<dim3(1, 32), 256>>>(out_sum, Wph,  bph,  out_ph,
                                                  M_ROWS, PHASE_N, D_MEM, nullptr);
    gemm_bias_act<0, false><<<dim3(1, 32), 256>>>(out_sum, Wmar, bmar, out_mar,
                                                  M_ROWS, MARGIN_N, D_MEM, nullptr);
}

// round 13
// speedup vs baseline: 3.8375x; 1.1214x over previous
#include <cuda_runtime.h>
#include <cuda_fp16.h>
#include <math.h>
#include <stdint.h>

// Problem constants
#define B_SZ    2
#define T_SEQ   1024
#define D_INF   1024
#define D_MEM   256
#define VOCAB   32000
#define PHASE_N 8
#define MARGIN_N 4
#define M_ROWS  (B_SZ * T_SEQ)   // 2048

// Output layout offsets (float elements)
#define OFF_MEM   0
#define OFF_SUM   131072
#define OFF_LB    655360
#define OFF_PH    66191360
#define OFF_WIN   66207744
#define OFF_MAR   131743744

// Scratch device globals
__device__ float g_k   [M_ROWS * D_MEM];
__device__ float g_v   [M_ROWS * D_MEM];
__device__ float g_beta[M_ROWS * D_MEM];
__device__ float g_lam [M_ROWS * D_MEM];
__device__ float g_sraw[M_ROWS * D_MEM];
__device__ float g_G1  [B_SZ * T_SEQ];   // k_{t-1}.k_t
__device__ float g_G2  [B_SZ * T_SEQ];   // k_{t-2}.k_t
// fp16 operands for the vocab GEMMs
__device__ __half g_A16 [M_ROWS * D_MEM];          // fp16(summary)
__device__ __half g_W1f [(size_t)VOCAB * D_MEM];   // fp16(Wlb)
__device__ __half g_W2f [(size_t)VOCAB * D_MEM];   // fp16(Wwin)

// ===================== helpers =====================
__device__ __forceinline__ uint32_t smem_u32(const void* p) {
    uint32_t a;
    asm("{ .reg .u64 t; cvta.to.shared.u64 t, %1; cvt.u32.u64 %0, t; }" : "=r"(a) : "l"(p));
    return a;
}
__device__ __forceinline__ void cp_async16(uint32_t dst, const void* src) {
    asm volatile("cp.async.cg.shared.global [%0], [%1], 16;" :: "r"(dst), "l"(src));
}
#define CP_COMMIT() asm volatile("cp.async.commit_group;" ::: "memory")
#define CP_WAIT(N)  asm volatile("cp.async.wait_group %0;" :: "n"(N) : "memory")

__device__ __forceinline__ void ldsm4(uint32_t* r, uint32_t addr) {
    asm volatile("ldmatrix.sync.aligned.m8n8.x4.shared.b16 {%0,%1,%2,%3}, [%4];"
        : "=r"(r[0]), "=r"(r[1]), "=r"(r[2]), "=r"(r[3]) : "r"(addr));
}
__device__ __forceinline__ void mma16816h(float* c, const uint32_t* a,
                                          uint32_t b0, uint32_t b1) {
    asm volatile(
        "mma.sync.aligned.m16n8k16.row.col.f32.f16.f16.f32 "
        "{%0,%1,%2,%3}, {%4,%5,%6,%7}, {%8,%9}, {%0,%1,%2,%3};"
        : "+f"(c[0]), "+f"(c[1]), "+f"(c[2]), "+f"(c[3])
        : "r"(a[0]), "r"(a[1]), "r"(a[2]), "r"(a[3]), "r"(b0), "r"(b1));
}

// packed f32x2 (FFMA2)
__device__ __forceinline__ unsigned long long pack2(float x, float y) {
    unsigned long long r;
    asm("mov.b64 %0, {%1, %2};" : "=l"(r) : "f"(x), "f"(y));
    return r;
}
__device__ __forceinline__ void unpack2(unsigned long long p, float& x, float& y) {
    asm("mov.b64 {%0, %1}, %2;" : "=f"(x), "=f"(y) : "l"(p));
}
__device__ __forceinline__ void ffma2(unsigned long long& d, unsigned long long a,
                                      unsigned long long b) {
    asm("fma.rn.f32x2 %0, %1, %2, %0;" : "+l"(d) : "l"(a), "l"(b));
}

// ===================== generic SIMT GEMM (small heads + summary) =====================
template <int ACT, bool H16>
__global__ __launch_bounds__(256)
void gemm_bias_act(const float* __restrict__ A, const float* __restrict__ B,
                   const float* __restrict__ bias, float* __restrict__ C,
                   int M, int N, int K, __half* __restrict__ gh)
{
    __shared__ float As[16][68];
    __shared__ float Bs[16][68];

    const int tid = threadIdx.x;
    const int m0 = blockIdx.y * 64;
    const int n0 = blockIdx.x * 64;
    const int ty = tid >> 4;
    const int tx = tid & 15;
    const int lr = tid >> 2;
    const int lc = (tid & 3) << 2;

    unsigned long long acc[4][2];
    #pragma unroll
    for (int i = 0; i < 4; i++) { acc[i][0] = 0ull; acc[i][1] = 0ull; }

    for (int k0 = 0; k0 < K; k0 += 16) {
        float4 av = *(const float4*)(A + (size_t)(m0 + lr) * K + k0 + lc);
        float4 bv = make_float4(0.f, 0.f, 0.f, 0.f);
        int bn = n0 + lr;
        if (bn < N) bv = *(const float4*)(B + (size_t)bn * K + k0 + lc);

        As[lc + 0][lr] = av.x; As[lc + 1][lr] = av.y;
        As[lc + 2][lr] = av.z; As[lc + 3][lr] = av.w;
        Bs[lc + 0][lr] = bv.x; Bs[lc + 1][lr] = bv.y;
        Bs[lc + 2][lr] = bv.z; Bs[lc + 3][lr] = bv.w;
        __syncthreads();

        #pragma unroll
        for (int kk = 0; kk < 16; kk++) {
            float4 a4  = *(const float4*)&As[kk][ty << 2];
            float2 b01 = *(const float2*)&Bs[kk][tx << 2];
            float2 b23 = *(const float2*)&Bs[kk][(tx << 2) + 2];
            unsigned long long B01 = pack2(b01.x, b01.y);
            unsigned long long B23 = pack2(b23.x, b23.y);
            unsigned long long a0 = pack2(a4.x, a4.x);
            unsigned long long a1 = pack2(a4.y, a4.y);
            unsigned long long a2 = pack2(a4.z, a4.z);
            unsigned long long a3 = pack2(a4.w, a4.w);
            ffma2(acc[0][0], a0, B01); ffma2(acc[0][1], a0, B23);
            ffma2(acc[1][0], a1, B01); ffma2(acc[1][1], a1, B23);
            ffma2(acc[2][0], a2, B01); ffma2(acc[2][1], a2, B23);
            ffma2(acc[3][0], a3, B01); ffma2(acc[3][1], a3, B23);
        }
        __syncthreads();
    }

    #pragma unroll
    for (int i = 0; i < 4; i++) {
        int m = m0 + (ty << 2) + i;
        float cs[4];
        unpack2(acc[i][0], cs[0], cs[1]);
        unpack2(acc[i][1], cs[2], cs[3]);
        #pragma unroll
        for (int j = 0; j < 4; j++) {
            int n = n0 + (tx << 2) + j;
            if (n < N) {
                float c = cs[j] + bias[n];
                if (ACT == 1) c = 1.f / (1.f + __expf(-c));
                else if (ACT == 2) c = tanhf(c);
                cs[j] = c;
                C[(size_t)m * N + n] = c;
            }
        }
        if (H16) {
            int nb = n0 + (tx << 2);
            __half2* ph = (__half2*)(gh + (size_t)m * 256 + nb);
            ph[0] = __halves2half2(__float2half_rn(cs[0]), __float2half_rn(cs[1]));
            ph[1] = __halves2half2(__float2half_rn(cs[2]), __float2half_rn(cs[3]));
        }
    }
}

// ===================== merged projections (grid.z selects head) =====================
__global__ __launch_bounds__(256)
void proj_gemm(const float* __restrict__ A,
               const float* __restrict__ W0, const float* __restrict__ W1,
               const float* __restrict__ W2, const float* __restrict__ W3,
               const float* __restrict__ b0, const float* __restrict__ b1,
               const float* __restrict__ b2, const float* __restrict__ b3,
               float* __restrict__ C0, float* __restrict__ C1,
               float* __restrict__ C2, float* __restrict__ C3)
{
    const int z = blockIdx.z;
    const float* B; const float* bias; float* C; int act;
    switch (z) {
        case 0:  B = W0; bias = b0; C = C0; act = 0; break;
        case 1:  B = W1; bias = b1; C = C1; act = 0; break;
        case 2:  B = W2; bias = b2; C = C2; act = 1; break;
        default: B = W3; bias = b3; C = C3; act = 1; break;
    }
    const int K = D_INF, N = D_MEM;

    __shared__ float As[16][68];
    __shared__ float Bs[16][68];

    const int tid = threadIdx.x;
    const int m0 = blockIdx.y * 64;
    const int n0 = blockIdx.x * 64;
    const int ty = tid >> 4;
    const int tx = tid & 15;
    const int lr = tid >> 2;
    const int lc = (tid & 3) << 2;

    unsigned long long acc[4][2];
    #pragma unroll
    for (int i = 0; i < 4; i++) { acc[i][0] = 0ull; acc[i][1] = 0ull; }

    for (int k0 = 0; k0 < K; k0 += 16) {
        float4 av = *(const float4*)(A + (size_t)(m0 + lr) * K + k0 + lc);
        float4 bv = *(const float4*)(B + (size_t)(n0 + lr) * K + k0 + lc);
        As[lc + 0][lr] = av.x; As[lc + 1][lr] = av.y;
        As[lc + 2][lr] = av.z; As[lc + 3][lr] = av.w;
        Bs[lc + 0][lr] = bv.x; Bs[lc + 1][lr] = bv.y;
        Bs[lc + 2][lr] = bv.z; Bs[lc + 3][lr] = bv.w;
        __syncthreads();
        #pragma unroll
        for (int kk = 0; kk < 16; kk++) {
            float4 a4  = *(const float4*)&As[kk][ty << 2];
            float2 b01 = *(const float2*)&Bs[kk][tx << 2];
            float2 b23 = *(const float2*)&Bs[kk][(tx << 2) + 2];
            unsigned long long B01 = pack2(b01.x, b01.y);
            unsigned long long B23 = pack2(b23.x, b23.y);
            unsigned long long a0 = pack2(a4.x, a4.x);
            unsigned long long a1 = pack2(a4.y, a4.y);
            unsigned long long a2 = pack2(a4.z, a4.z);
            unsigned long long a3 = pack2(a4.w, a4.w);
            ffma2(acc[0][0], a0, B01); ffma2(acc[0][1], a0, B23);
            ffma2(acc[1][0], a1, B01); ffma2(acc[1][1], a1, B23);
            ffma2(acc[2][0], a2, B01); ffma2(acc[2][1], a2, B23);
            ffma2(acc[3][0], a3, B01); ffma2(acc[3][1], a3, B23);
        }
        __syncthreads();
    }

    #pragma unroll
    for (int i = 0; i < 4; i++) {
        int m = m0 + (ty << 2) + i;
        float cs[4];
        unpack2(acc[i][0], cs[0], cs[1]);
        unpack2(acc[i][1], cs[2], cs[3]);
        #pragma unroll
        for (int j = 0; j < 4; j++) {
            int n = n0 + (tx << 2) + j;
            float c = cs[j] + bias[n];
            if (act == 1) c = 1.f / (1.f + __expf(-c));
            C[(size_t)m * N + n] = c;
        }
    }
}

// ===================== weight fp16 pre-convert (merged, grid.z selects W) ======
__global__ __launch_bounds__(256)
void convert_w16(const float* __restrict__ W1, const float* __restrict__ W2,
                 __half* __restrict__ o1, __half* __restrict__ o2)
{
    const float* W = blockIdx.z ? W2 : W1;
    __half* o = blockIdx.z ? o2 : o1;
    int i = blockIdx.x * 256 + threadIdx.x;     // [0, 32000*64)
    int n  = i >> 6;
    int kq = (i & 63) << 2;
    float4 w = *(const float4*)(W + (size_t)n * 256 + kq);
    size_t off = (size_t)n * 256 + kq;
    ((__half2*)(o + off))[0] = __halves2half2(__float2half_rn(w.x), __float2half_rn(w.y));
    ((__half2*)(o + off))[1] = __halves2half2(__float2half_rn(w.z), __float2half_rn(w.w));
}

// ===================== mma.sync vocab GEMM (fp16, 1-term) =====================
#define VK_PAD    40
#define VK_TILE   (128 * VK_PAD * 2)
#define VK_STAGE  (2 * VK_TILE)
#define VK_NSTAGE 4
#define VK_SMEM   (VK_NSTAGE * VK_STAGE)   // 81920

__global__ __launch_bounds__(256, 2)
void vocab_mma(const __half* __restrict__ gA,
               const __half* __restrict__ gB1, const __half* __restrict__ gB2,
               const float* __restrict__ bias1, const float* __restrict__ bias2,
               float* __restrict__ C1, float* __restrict__ C2)
{
    extern __shared__ __align__(16) char smem_raw[];
    const __half* gB = blockIdx.z ? gB2 : gB1;
    const float* bias = blockIdx.z ? bias2 : bias1;
    float* C = blockIdx.z ? C2 : C1;

    const int tid  = threadIdx.x;
    const int warp = tid >> 5, lane = tid & 31;
    const int wm = warp >> 2, wn = warp & 3;
    const int m0 = blockIdx.y * 128, n0 = blockIdx.x * 128;

    const uint32_t sbase = smem_u32(smem_raw);

    const int lrow = tid >> 1;
    const int lhal = tid & 1;

    float acc[4][4][4];
    #pragma unroll
    for (int i = 0; i < 4; i++)
        #pragma unroll
        for (int j = 0; j < 4; j++) {
            acc[i][j][0] = 0.f; acc[i][j][1] = 0.f;
            acc[i][j][2] = 0.f; acc[i][j][3] = 0.f;
        }

    auto issue_stage = [&](int kc) {
        const uint32_t st = sbase + (kc % VK_NSTAGE) * VK_STAGE;
        const size_t gAo = (size_t)(m0 + lrow) * 256 + kc * 32 + lhal * 16;
        const size_t gBo = (size_t)(n0 + lrow) * 256 + kc * 32 + lhal * 16;
        const uint32_t sd = st + lrow * (VK_PAD * 2) + lhal * 32;
        cp_async16(sd + 0 * VK_TILE,      gA + gAo);
        cp_async16(sd + 0 * VK_TILE + 16, gA + gAo + 8);
        cp_async16(sd + 1 * VK_TILE,      gB + gBo);
        cp_async16(sd + 1 * VK_TILE + 16, gB + gBo + 8);
    };

    issue_stage(0); CP_COMMIT();
    issue_stage(1); CP_COMMIT();
    issue_stage(2); CP_COMMIT();

    const uint32_t ar = wm * 64 + (lane & 15);
    const uint32_t ac16 = (lane >> 4) * 8;
    const int g = lane >> 3, r8 = lane & 7;
    const uint32_t br = wn * 32 + ((g >> 1) * 8) + r8;
    const uint32_t bc = (g & 1) * 8;

    #pragma unroll
    for (int kc = 0; kc < 8; kc++) {
        if (kc < 5)      { issue_stage(kc + 3); CP_COMMIT(); CP_WAIT(3); }
        else if (kc == 5){ CP_WAIT(2); }
        else if (kc == 6){ CP_WAIT(1); }
        else             { CP_WAIT(0); }
        __syncthreads();

        const uint32_t st = sbase + (kc % VK_NSTAGE) * VK_STAGE;
        const uint32_t tA = st;
        const uint32_t tB = st + VK_TILE;

        #pragma unroll
        for (int h = 0; h < 2; h++) {
            uint32_t a[4][4], b[2][4];
            #pragma unroll
            for (int fm = 0; fm < 4; fm++)
                ldsm4(a[fm], tA + ((ar + fm * 16) * VK_PAD + ac16 + h * 16) * 2);
            #pragma unroll
            for (int p = 0; p < 2; p++)
                ldsm4(b[p], tB + ((br + p * 16) * VK_PAD + bc + h * 16) * 2);

            #pragma unroll
            for (int fm = 0; fm < 4; fm++)
                #pragma unroll
                for (int fn = 0; fn < 4; fn++) {
                    const int p = fn >> 1, q = fn & 1;
                    mma16816h(acc[fm][fn], a[fm], b[p][q * 2], b[p][q * 2 + 1]);
                }
        }
        __syncthreads();
    }

    float2 bv[4];
    #pragma unroll
    for (int fn = 0; fn < 4; fn++)
        bv[fn] = *(const float2*)(bias + n0 + wn * 32 + fn * 8 + (lane & 3) * 2);

    #pragma unroll
    for (int fm = 0; fm < 4; fm++) {
        const int r0 = m0 + wm * 64 + fm * 16 + (lane >> 2);
        #pragma unroll
        for (int fn = 0; fn < 4; fn++) {
            const int col = n0 + wn * 32 + fn * 8 + (lane & 3) * 2;
            float2 v0 = make_float2(acc[fm][fn][0] + bv[fn].x, acc[fm][fn][1] + bv[fn].y);
            float2 v1 = make_float2(acc[fm][fn][2] + bv[fn].x, acc[fm][fn][3] + bv[fn].y);
            *(float2*)(C + (size_t)r0 * VOCAB + col)       = v0;
            *(float2*)(C + (size_t)(r0 + 8) * VOCAB + col) = v1;
        }
    }
}

// ===================== row L2-normalize =====================
__global__ __launch_bounds__(256)
void normalize_rows(float* __restrict__ X)
{
    int w = (blockIdx.x * blockDim.x + threadIdx.x) >> 5;
    int lane = threadIdx.x & 31;
    if (w >= M_ROWS) return;
    float* row = X + (size_t)w * D_MEM;
    float x[8];
    float ss = 0.f;
    #pragma unroll
    for (int j = 0; j < 8; j++) { x[j] = row[lane + 32 * j]; ss += x[j] * x[j]; }
    #pragma unroll
    for (int o = 16; o; o >>= 1) ss += __shfl_xor_sync(0xffffffffu, ss, o);
    float inv = 1.f / fmaxf(sqrtf(ss), 1e-12f);
    #pragma unroll
    for (int j = 0; j < 8; j++) row[lane + 32 * j] = x[j] * inv;
}

// ===================== k-neighbor Gram precompute ============================
// G1[b][t] = k_{t-1}.k_t (t>=1), G2[b][t] = k_{t-2}.k_t (t>=2); else 0.
// One warp per (b,t): 2048 warps. Row-independent -> removes 2 of 3 warp
// reductions per scan step for all 512 scan warps.
__global__ __launch_bounds__(256)
void gram_kernel(const float* __restrict__ Kn, float* __restrict__ G1,
                 float* __restrict__ G2)
{
    int w = (blockIdx.x * blockDim.x + threadIdx.x) >> 5;  // 0..2047
    int lane = threadIdx.x & 31;
    int b = w >> 10, t = w & 1023;
    const float* kt = Kn + (size_t)b * T_SEQ * D_MEM + (size_t)t * D_MEM + lane;
    float d1a = 0.f, d1b = 0.f, d2a = 0.f, d2b = 0.f;
    #pragma unroll
    for (int j = 0; j < 8; j += 2) {
        float a0 = kt[32 * j], a1 = kt[32 * (j + 1)];
        float p0 = (t >= 1) ? kt[32 * j - D_MEM] : 0.f;
        float p1 = (t >= 1) ? kt[32 * (j + 1) - D_MEM] : 0.f;
        float q0 = (t >= 2) ? kt[32 * j - 2 * D_MEM] : 0.f;
        float q1 = (t >= 2) ? kt[32 * (j + 1) - 2 * D_MEM] : 0.f;
        d1a += a0 * p0; d1b += a1 * p1;
        d2a += a0 * q0; d2b += a1 * q1;
    }
    float d1 = d1a + d1b, d2 = d2a + d2b;
    #pragma unroll
    for (int o = 16; o; o >>= 1) {
        d1 += __shfl_xor_sync(0xffffffffu, d1, o);
        d2 += __shfl_xor_sync(0xffffffffu, d2, o);
    }
    if (lane == 0) { G1[w] = d1; G2[w] = d2; }
}

// ===================== gated delta-rule scan (distance-2 pipelined) ===========
// read_s = l_{s-1}l_{s-2}*D_s + l_{s-1}corr_{s-2}*G2_s + corr_{s-1}*G1_s
// D_s = M_{s-2}.k_s : its butterfly gets 2 iterations of slack.
// G1/G2 are precomputed (k-only). One butterfly per step. All rings static
// (ring-of-4 via token pasting + 4x unrolled loop) -> no local-memory spill.
#define SCAN_BODY(C, C2, S) do {                                              \
    const int ii_ = ((S) + 4 < T_SEQ) ? (S) + 4 : (T_SEQ - 1);                \
    float nk_[8];                                                             \
    _Pragma("unroll")                                                         \
    for (int j = 0; j < 8; j++) nk_[j] = kb[(size_t)ii_ * D_MEM + 32 * j];    \
    const float nv_ = vb[(size_t)ii_ * D_MEM];                                \
    const float nb_ = bbp[(size_t)ii_ * D_MEM];                               \
    const float nl_ = lb[(size_t)ii_ * D_MEM];                                \
    const float ng1_ = g1b[ii_], ng2_ = g2b[ii_];                             \
    float ua_ = 0.f, ub_ = 0.f;                                               \
    _Pragma("unroll")                                                         \
    for (int j = 0; j < 8; j += 2) {                                          \
        ua_ += m[j] * kr##C2[j];                                              \
        ub_ += m[j + 1] * kr##C2[j + 1];                                      \
    }                                                                         \
    const float base_ = fmaf(t12, D0, t2 * g2r##C);                           \
    const float read_ = fmaf(c1, g1r##C, base_);                              \
    const float corr_ = (vr##C - read_) * br##C;                              \
    if (lane == 0) sb[(size_t)(S) * D_MEM] = fmaf(lr##C, read_, corr_);       \
    _Pragma("unroll")                                                         \
    for (int j = 0; j < 8; j++)                                               \
        m[j] = fmaf(m[j], lr##C, corr_ * kr##C[j]);                           \
    _Pragma("unroll")                                                         \
    for (int o = 16; o; o >>= 1) {                                            \
        ua_ += __shfl_xor_sync(0xffffffffu, ua_, o);                          \
        ub_ += __shfl_xor_sync(0xffffffffu, ub_, o);                          \
    }                                                                         \
    const float t12n_ = lr##C * l1;                                           \
    const float t2n_  = lr##C * c1;                                           \
    l1 = lr##C; c1 = corr_; t12 = t12n_; t2 = t2n_;                           \
    D0 = D1r; D1r = ua_ + ub_;                                                \
    _Pragma("unroll")                                                         \
    for (int j = 0; j < 8; j++) kr##C[j] = nk_[j];                            \
    vr##C = nv_; br##C = nb_; lr##C = nl_;                                    \
    g1r##C = ng1_; g2r##C = ng2_;                                             \
} while (0)

__global__ __launch_bounds__(128)
void scan_kernel(const float* __restrict__ Kn, const float* __restrict__ V,
                 const float* __restrict__ Beta, const float* __restrict__ Lam,
                 const float* __restrict__ G1, const float* __restrict__ G2,
                 const float* __restrict__ Mem0, float* __restrict__ Sraw,
                 float* __restrict__ MemOut)
{
    const int wid  = threadIdx.x >> 5;
    const int lane = threadIdx.x & 31;
    const int wg = blockIdx.x * 4 + wid;
    const int b = wg >> 8;
    const int r = wg & 255;

    const float* kb  = Kn   + (size_t)b * T_SEQ * D_MEM + lane;
    const float* vb  = V    + (size_t)b * T_SEQ * D_MEM + r;
    const float* bbp = Beta + (size_t)b * T_SEQ * D_MEM + r;
    const float* lb  = Lam  + (size_t)b * T_SEQ * D_MEM + r;
    const float* g1b = G1 + (size_t)b * T_SEQ;
    const float* g2b = G2 + (size_t)b * T_SEQ;
    float* sb = Sraw + (size_t)b * T_SEQ * D_MEM + r;

    float m[8];
    #pragma unroll
    for (int j = 0; j < 8; j++)
        m[j] = Mem0[(size_t)b * D_MEM * D_MEM + (size_t)r * D_MEM + lane + 32 * j];

    // rings (all static)
    float kr0[8], kr1[8], kr2[8], kr3[8];
    #pragma unroll
    for (int j = 0; j < 8; j++) {
        kr0[j] = kb[32 * j];
        kr1[j] = kb[D_MEM + 32 * j];
        kr2[j] = kb[2 * D_MEM + 32 * j];
        kr3[j] = kb[3 * D_MEM + 32 * j];
    }
    float vr0 = vb[0], vr1 = vb[D_MEM], vr2 = vb[2 * D_MEM], vr3 = vb[3 * D_MEM];
    float br0 = bbp[0], br1 = bbp[D_MEM], br2 = bbp[2 * D_MEM], br3 = bbp[3 * D_MEM];
    float lr0 = lb[0], lr1 = lb[D_MEM], lr2 = lb[2 * D_MEM], lr3 = lb[3 * D_MEM];
    float g1r0 = g1b[0], g1r1 = g1b[1], g1r2 = g1b[2], g1r3 = g1b[3];
    float g2r0 = g2b[0], g2r1 = g2b[1], g2r2 = g2b[2], g2r3 = g2b[3];

    // ---- boot: s = 0 and s = 1 ----
    // three interleaved reductions off M_0: read_0, A = M_0.k_1, Bv = M_0.k_2
    float pa = 0.f, pb = 0.f, Aa = 0.f, Ab = 0.f, Ba = 0.f, Bb = 0.f;
    #pragma unroll
    for (int j = 0; j < 8; j += 2) {
        pa += m[j] * kr0[j];     pb += m[j + 1] * kr0[j + 1];
        Aa += m[j] * kr1[j];     Ab += m[j + 1] * kr1[j + 1];
        Ba += m[j] * kr2[j];     Bb += m[j + 1] * kr2[j + 1];
    }
    float p = pa + pb, A = Aa + Ab, Bv = Ba + Bb;
    #pragma unroll
    for (int o = 16; o; o >>= 1) {
        p  += __shfl_xor_sync(0xffffffffu, p,  o);
        A  += __shfl_xor_sync(0xffffffffu, A,  o);
        Bv += __shfl_xor_sync(0xffffffffu, Bv, o);
    }
    // s = 0
    const float read0 = p;
    const float corr0 = (vr0 - read0) * br0;
    if (lane == 0) sb[0] = fmaf(lr0, read0, corr0);
    const float l0 = lr0;
    #pragma unroll
    for (int j = 0; j < 8; j++) m[j] = fmaf(m[j], l0, corr0 * kr0[j]);   // m = M_1
    // reload slot 0 <- step 4
    #pragma unroll
    for (int j = 0; j < 8; j++) kr0[j] = kb[4 * D_MEM + 32 * j];
    vr0 = vb[4 * D_MEM]; br0 = bbp[4 * D_MEM]; lr0 = lb[4 * D_MEM];
    g1r0 = g1b[4]; g2r0 = g2b[4];

    // s = 1 (distance-1 form): read_1 = l0*(M_0.k_1) + corr_0*(k_0.k_1)
    const float read1 = fmaf(l0, A, corr0 * g1r1);
    const float corr1 = (vr1 - read1) * br1;
    if (lane == 0) sb[D_MEM] = fmaf(lr1, read1, corr1);
    // D_3 partials with m = M_1 (pre-update)
    float ua = 0.f, ub = 0.f;
    #pragma unroll
    for (int j = 0; j < 8; j += 2) {
        ua += m[j] * kr3[j];
        ub += m[j + 1] * kr3[j + 1];
    }
    const float l1v = lr1;
    #pragma unroll
    for (int j = 0; j < 8; j++) m[j] = fmaf(m[j], l1v, corr1 * kr1[j]);  // m = M_2
    #pragma unroll
    for (int o = 16; o; o >>= 1) {
        ua += __shfl_xor_sync(0xffffffffu, ua, o);
        ub += __shfl_xor_sync(0xffffffffu, ub, o);
    }
    const float D3 = ua + ub;
    // reload slot 1 <- step 5
    #pragma unroll
    for (int j = 0; j < 8; j++) kr1[j] = kb[5 * D_MEM + 32 * j];
    vr1 = vb[5 * D_MEM]; br1 = bbp[5 * D_MEM]; lr1 = lb[5 * D_MEM];
    g1r1 = g1b[5]; g2r1 = g2b[5];

    // steady-state scalar init (entering s = 2)
    float D0 = Bv;              // D_2 = M_0.k_2
    float D1r = D3;             // D_3 = M_1.k_3
    float c1 = corr1;           // corr_{s-1}
    float t12 = l1v * l0;       // l_{s-1} * l_{s-2}
    float t2 = l1v * corr0;     // l_{s-1} * corr_{s-2}
    float l1 = l1v;             // l_{s-1}

    SCAN_BODY(2, 0, 2);
    SCAN_BODY(3, 1, 3);
    for (int s = 4; s < T_SEQ; s += 4) {
        SCAN_BODY(0, 2, s);
        SCAN_BODY(1, 3, s + 1);
        SCAN_BODY(2, 0, s + 2);
        SCAN_BODY(3, 1, s + 3);
    }

    #pragma unroll
    for (int j = 0; j < 8; j++)
        MemOut[(size_t)b * D_MEM * D_MEM + (size_t)r * D_MEM + lane + 32 * j] = m[j];
}

// ===================== launch =====================
extern "C" void kernel_launch(void* const* d_in, const int* in_sizes, int n_in,
                              void* d_out, int out_size)
{
    const float* cf    = (const float*)d_in[0];
    const float* mem0  = (const float*)d_in[1];
    const float* Wk    = (const float*)d_in[2];
    const float* bk    = (const float*)d_in[3];
    const float* Wv    = (const float*)d_in[4];
    const float* bv    = (const float*)d_in[5];
    const float* Wbeta = (const float*)d_in[6];
    const float* bbeta = (const float*)d_in[7];
    const float* Wlam  = (const float*)d_in[8];
    const float* blam  = (const float*)d_in[9];
    const float* Wsum  = (const float*)d_in[10];
    const float* bsum  = (const float*)d_in[11];
    const float* Wlb   = (const float*)d_in[12];
    const float* blb   = (const float*)d_in[13];
    const float* Wph   = (const float*)d_in[14];
    const float* bph   = (const float*)d_in[15];
    const float* Wwin  = (const float*)d_in[16];
    const float* bwin  = (const float*)d_in[17];
    const float* Wmar  = (const float*)d_in[18];
    const float* bmar  = (const float*)d_in[19];

    float* out = (float*)d_out;
    float* out_mem = out + OFF_MEM;
    float* out_sum = out + OFF_SUM;
    float* out_lb  = out + OFF_LB;
    float* out_ph  = out + OFF_PH;
    float* out_win = out + OFF_WIN;
    float* out_mar = out + OFF_MAR;

    float *pk, *pv, *pb, *pl, *ps, *pG1, *pG2;
    __half *pA16, *pW1, *pW2;
    cudaGetSymbolAddress((void**)&pk, g_k);
    cudaGetSymbolAddress((void**)&pv, g_v);
    cudaGetSymbolAddress((void**)&pb, g_beta);
    cudaGetSymbolAddress((void**)&pl, g_lam);
    cudaGetSymbolAddress((void**)&ps, g_sraw);
    cudaGetSymbolAddress((void**)&pG1, g_G1);
    cudaGetSymbolAddress((void**)&pG2, g_G2);
    cudaGetSymbolAddress((void**)&pA16, g_A16);
    cudaGetSymbolAddress((void**)&pW1, g_W1f);
    cudaGetSymbolAddress((void**)&pW2, g_W2f);

    cudaFuncSetAttribute(vocab_mma, cudaFuncAttributeMaxDynamicSharedMemorySize, VK_SMEM);

    // weight pre-convert (merged; independent of the recurrence path)
    convert_w16<<<dim3(8000, 1, 2), 256>>>(Wlb, Wwin, pW1, pW2);

    // projections (merged)
    proj_gemm<<<dim3(4, 32, 4), 256>>>(cf, Wk, Wv, Wbeta, Wlam,
                                       bk, bv, bbeta, blam,
                                       pk, pv, pb, pl);

    normalize_rows<<<256, 256>>>(pk);

    // k-neighbor Gram terms (2048 warps)
    gram_kernel<<<256, 256>>>(pk, pG1, pG2);

    scan_kernel<<<128, 128>>>(pk, pv, pb, pl, pG1, pG2, mem0, ps, out_mem);

    // summary GEMM (tanh) + fp16 side output
    gemm_bias_act<2, true><<<dim3(4, 32), 256>>>(ps, Wsum, bsum, out_sum,
                                                 M_ROWS, D_MEM, D_MEM, pA16);

    // both vocab GEMMs in one launch (grid.z selects head)
    vocab_mma<<<dim3(250, 16, 2), 256, VK_SMEM>>>(pA16, pW1, pW2, blb, bwin,
                                                  out_lb, out_win);

    // small heads
    gemm_bias_act<0, false><<<dim3(1, 32), 256>>>(out_sum, Wph,  bph,  out_ph,
                                                  M_ROWS, PHASE_N, D_MEM, nullptr);
    gemm_bias_act<0, false><<<dim3(1, 32), 256>>>(out_sum, Wmar, bmar, out_mar,
                                                  M_ROWS, MARGIN_N, D_MEM, nullptr);
}